// round 13
// baseline (speedup 1.0000x reference)
#include <cuda_runtime.h>
#include <cuda_bf16.h>
#include <cstdint>

// ---------------------------------------------------------------------------
// PositionRelationEncodeUnit_GCN — mma.sync (split-bf16, 3-term) implementation
//
//   h[i,j,:]  = A1[i,:] + B1[j,:] + bbox[i,j,:] @ w1c^T
//   logit[i,j]= c0 + sum_h u[h]*leaky(h[i,j,h])
//   conf      = renorm(mask * softmax_j(logit))
//   g[i,j,:]  = relu(Ac[i,:] + Bc[j,:] + bbox[i,j,:] @ cw1c^T)
//   G[i,:]    = sum_j conf[i,j]*g[i,j,:]
//   out[i,:]  = G[i,:] @ cw2^T + cb2 * sum_j conf[i,j]
//
// Per-pair GEMMs on HMMA (mma.sync.m16n8k16.bf16, fp32 acc), split-bf16:
//   A@B ≈ Ahi@Bhi + Alo@Bhi + Ahi@Blo   (virtual K = 3*128 = 384)
// A/B operands are pre-packed in gmem in the exact mma.sync per-lane
// fragment layout, so the mainloop is pure LDG.128 + HMMA.
// ---------------------------------------------------------------------------

#define NN   512
#define HID  256
#define DB   128

// ----- device scratch -----
__device__ __align__(16) float g_A1[NN * HID];
__device__ __align__(16) float g_B1[NN * HID];
__device__ __align__(16) float g_Ac[NN * HID];
__device__ __align__(16) float g_Bc[NN * HID];
__device__ float g_u[HID];
__device__ float g_c0;
__device__ __align__(16) float g_logits[NN * NN];
__device__ __align__(16) float g_conf[NN * NN];
__device__ float g_ssum[NN];
__device__ __align__(16) float g_Gpart[4 * NN * HID];
__device__ __align__(16) float g_G[NN * HID];

// A fragments: [i (512)][jm (32)][kt (8)][lane (32)] x uint4  (hi and lo)
// index: (((i*32 + jm)*8 + kt)*32 + lane)
__device__ uint4 g_Afh[NN * 32 * 8 * 32];
__device__ uint4 g_Afl[NN * 32 * 8 * 32];
// B fragments: [mat (2)][prec (2)][ ((kt*4+hw)*4+np)*32 + lane ] x uint4
__device__ uint4 g_Bf[2][2][8 * 4 * 4 * 32];

// ----- helpers -----
__device__ __forceinline__ uint32_t pk2(__nv_bfloat16 a, __nv_bfloat16 b) {
    return (uint32_t)__bfloat16_as_ushort(a) |
           ((uint32_t)__bfloat16_as_ushort(b) << 16);
}
__device__ __forceinline__ void splt(float v, __nv_bfloat16& hi, __nv_bfloat16& lo) {
    hi = __float2bfloat16(v);
    lo = __float2bfloat16(v - __bfloat162float(hi));
}
__device__ __forceinline__ void mma16816(float* c, const uint32_t* a,
                                         uint32_t b0, uint32_t b1) {
    asm volatile(
        "mma.sync.aligned.m16n8k16.row.col.f32.bf16.bf16.f32 "
        "{%0,%1,%2,%3}, {%4,%5,%6,%7}, {%8,%9}, {%0,%1,%2,%3};"
        : "+f"(c[0]), "+f"(c[1]), "+f"(c[2]), "+f"(c[3])
        : "r"(a[0]), "r"(a[1]), "r"(a[2]), "r"(a[3]), "r"(b0), "r"(b1));
}

// ---------------------------------------------------------------------------
// Precompute A1/B1/Ac/Bc (object-feature halves of the first Linears)
// ---------------------------------------------------------------------------
__global__ void __launch_bounds__(256) k_rowmlp(const float* __restrict__ obj,
                                                const float* __restrict__ w1,
                                                const float* __restrict__ b1,
                                                const float* __restrict__ cw1,
                                                const float* __restrict__ cb1) {
    __shared__ float s_obj[4 * 256];
    const int i0 = blockIdx.x * 4;
    const int tid = threadIdx.x;
#pragma unroll
    for (int r = 0; r < 4; ++r) s_obj[r * 256 + tid] = obj[(i0 + r) * 256 + tid];
    __syncthreads();

    const int h = tid;
    float aA[4] = {0.f, 0.f, 0.f, 0.f}, aB[4] = {0.f, 0.f, 0.f, 0.f};
    float aC[4] = {0.f, 0.f, 0.f, 0.f}, aD[4] = {0.f, 0.f, 0.f, 0.f};
    const float4* wr = (const float4*)(w1 + (size_t)h * 640);
    const float4* cr = (const float4*)(cw1 + (size_t)h * 640);
#pragma unroll 4
    for (int k4 = 0; k4 < 64; ++k4) {
        float4 wa = wr[k4], wb = wr[64 + k4];
        float4 ca = cr[k4], cb = cr[64 + k4];
#pragma unroll
        for (int r = 0; r < 4; ++r) {
            const float* o = s_obj + r * 256 + k4 * 4;
            float o0 = o[0], o1 = o[1], o2 = o[2], o3 = o[3];
            aA[r] += wa.x * o0 + wa.y * o1 + wa.z * o2 + wa.w * o3;
            aB[r] += wb.x * o0 + wb.y * o1 + wb.z * o2 + wb.w * o3;
            aC[r] += ca.x * o0 + ca.y * o1 + ca.z * o2 + ca.w * o3;
            aD[r] += cb.x * o0 + cb.y * o1 + cb.z * o2 + cb.w * o3;
        }
    }
    const float bb1 = b1[h], bcb1 = cb1[h];
#pragma unroll
    for (int r = 0; r < 4; ++r) {
        g_A1[(i0 + r) * 256 + h] = aA[r] + bb1;
        g_B1[(i0 + r) * 256 + h] = aB[r];
        g_Ac[(i0 + r) * 256 + h] = aC[r] + bcb1;
        g_Bc[(i0 + r) * 256 + h] = aD[r];
    }
}

// Fold BN+w2 into (u, c0)
__global__ void k_uc0(const float* __restrict__ gamma, const float* __restrict__ beta,
                      const float* __restrict__ mean, const float* __restrict__ var,
                      const float* __restrict__ w2, const float* __restrict__ b2) {
    const int h = threadIdx.x;
    float rs = rsqrtf(var[h] + 1e-5f);
    float sc = gamma[h] * rs;
    g_u[h] = sc * w2[h];
    float t = (beta[h] - mean[h] * sc) * w2[h];
    __shared__ float sr[256];
    sr[h] = t;
    __syncthreads();
    for (int s = 128; s > 0; s >>= 1) {
        if (h < s) sr[h] += sr[h + s];
        __syncthreads();
    }
    if (h == 0) g_c0 = sr[0] + b2[0];
}

// ---------------------------------------------------------------------------
// B fragments. grid (8 kt, 4 hw, 2 mat), block 128 (4 np x 32 lanes)
// b0 = B[k0][n]|B[k0+1][n], b1 = B[k0+8][n]|B[k0+9][n]; n = t4-group, k = lanes
// ---------------------------------------------------------------------------
__global__ void k_bfrag(const float* __restrict__ w1, const float* __restrict__ cw1) {
    const int kt = blockIdx.x, hw = blockIdx.y, mat = blockIdx.z;
    const int np = threadIdx.x >> 5, lane = threadIdx.x & 31;
    const int g = lane >> 2, t4 = lane & 3;
    const float* W = mat ? cw1 : w1;
    const int n0 = hw * 64 + np * 16 + g;
    const int n1 = n0 + 8;
    const int k0 = kt * 16 + t4 * 2;
    const float* r0 = W + (size_t)n0 * 640 + 512;
    const float* r1 = W + (size_t)n1 * 640 + 512;
    __nv_bfloat16 h00a, l00a, h00b, l00b, h01a, l01a, h01b, l01b;
    __nv_bfloat16 h10a, l10a, h10b, l10b, h11a, l11a, h11b, l11b;
    splt(r0[k0], h00a, l00a);     splt(r0[k0 + 1], h00b, l00b);
    splt(r0[k0 + 8], h01a, l01a); splt(r0[k0 + 9], h01b, l01b);
    splt(r1[k0], h10a, l10a);     splt(r1[k0 + 1], h10b, l10b);
    splt(r1[k0 + 8], h11a, l11a); splt(r1[k0 + 9], h11b, l11b);
    const int idx = ((kt * 4 + hw) * 4 + np) * 32 + lane;
    g_Bf[mat][0][idx] = make_uint4(pk2(h00a, h00b), pk2(h01a, h01b),
                                   pk2(h10a, h10b), pk2(h11a, h11b));
    g_Bf[mat][1][idx] = make_uint4(pk2(l00a, l00b), pk2(l01a, l01b),
                                   pk2(l10a, l10b), pk2(l11a, l11b));
}

// ---------------------------------------------------------------------------
// A fragments from bbox. grid (32 jm, 512 i), block 256 (8 kt x 32 lanes)
// a0=(g,k0 pair) a1=(g+8,k0) a2=(g,k0+8) a3=(g+8,k0+8)
// ---------------------------------------------------------------------------
__global__ void __launch_bounds__(256) k_afrag(const float* __restrict__ bbox) {
    const int kt = threadIdx.x >> 5, lane = threadIdx.x & 31;
    const int jm = blockIdx.x, i = blockIdx.y;
    const int g = lane >> 2, t4 = lane & 3;
    const float* base = bbox + ((size_t)i * NN + (size_t)jm * 16) * DB;
    const int c0 = kt * 16 + t4 * 2;
    float2 v00 = *(const float2*)(base + (size_t)g * DB + c0);
    float2 v01 = *(const float2*)(base + (size_t)g * DB + c0 + 8);
    float2 v10 = *(const float2*)(base + (size_t)(g + 8) * DB + c0);
    float2 v11 = *(const float2*)(base + (size_t)(g + 8) * DB + c0 + 8);
    __nv_bfloat16 h0a, l0a, h0b, l0b, h1a, l1a, h1b, l1b;
    __nv_bfloat16 h2a, l2a, h2b, l2b, h3a, l3a, h3b, l3b;
    splt(v00.x, h0a, l0a); splt(v00.y, h0b, l0b);
    splt(v10.x, h1a, l1a); splt(v10.y, h1b, l1b);
    splt(v01.x, h2a, l2a); splt(v01.y, h2b, l2b);
    splt(v11.x, h3a, l3a); splt(v11.y, h3b, l3b);
    const size_t idx = (((size_t)i * 32 + jm) * 8 + kt) * 32 + lane;
    g_Afh[idx] = make_uint4(pk2(h0a, h0b), pk2(h1a, h1b), pk2(h2a, h2b), pk2(h3a, h3b));
    g_Afl[idx] = make_uint4(pk2(l0a, l0b), pk2(l1a, l1b), pk2(l2a, l2b), pk2(l3a, l3b));
}

// ---------------------------------------------------------------------------
// Tensor mainloop (shared by both passes): acc[2 mm][8 nt][4]
// block: 512 thr, 16 warps = 4 (wj) x 4 (wh); warp tile 32j x 64h, K=384
// ---------------------------------------------------------------------------
__device__ __forceinline__ void mma_mainloop(float acc[2][8][4], int i, int jt,
                                             int wj, int wh, int lane, int mat) {
    const int jm0 = jt * 8 + wj * 2;
    const uint4* As[3] = {g_Afh, g_Afl, g_Afh};
    const uint4* Bs[3] = {g_Bf[mat][0], g_Bf[mat][0], g_Bf[mat][1]};
#pragma unroll
    for (int t = 0; t < 3; ++t) {
        const uint4* pa0 = As[t] + (((size_t)i * 32 + jm0) * 8) * 32 + lane;
        const uint4* pa1 = pa0 + 8 * 32;
        const uint4* pb = Bs[t] + wh * 128 + lane;
#pragma unroll
        for (int kt = 0; kt < 8; ++kt) {
            uint4 a0 = pa0[kt * 32];
            uint4 a1 = pa1[kt * 32];
#pragma unroll
            for (int np = 0; np < 4; ++np) {
                uint4 bq = pb[kt * 512 + np * 32];
                mma16816(acc[0][np * 2 + 0], (const uint32_t*)&a0, bq.x, bq.y);
                mma16816(acc[1][np * 2 + 0], (const uint32_t*)&a1, bq.x, bq.y);
                mma16816(acc[0][np * 2 + 1], (const uint32_t*)&a0, bq.z, bq.w);
                mma16816(acc[1][np * 2 + 1], (const uint32_t*)&a1, bq.z, bq.w);
            }
        }
    }
}

// ---------------------------------------------------------------------------
// Pass 1: logits. grid (4 jt, 512 i), block 512
// ---------------------------------------------------------------------------
__global__ void __launch_bounds__(512, 1) k_pass1_m() {
    __shared__ float s_u[256], s_a1[256], sp[4][128];
    const int tid = threadIdx.x;
    const int lane = tid & 31, w = tid >> 5, wj = w >> 2, wh = w & 3;
    const int g = lane >> 2, t4 = lane & 3;
    const int jt = blockIdx.x, i = blockIdx.y;
    if (tid < 256) {
        s_u[tid] = g_u[tid];
        s_a1[tid] = g_A1[i * 256 + tid];
    }
    __syncthreads();

    float acc[2][8][4];
#pragma unroll
    for (int a = 0; a < 2; ++a)
#pragma unroll
        for (int b = 0; b < 8; ++b)
#pragma unroll
            for (int c = 0; c < 4; ++c) acc[a][b][c] = 0.f;

    mma_mainloop(acc, i, jt, wj, wh, lane, 0);

    const float c0v = g_c0;
#pragma unroll
    for (int mm = 0; mm < 2; ++mm) {
#pragma unroll
        for (int hf = 0; hf < 2; ++hf) {
            const int jl = wj * 32 + mm * 16 + g + hf * 8;
            const int jgl = jt * 128 + jl;
            const float* b1row = g_B1 + (size_t)jgl * 256;
            float s = 0.f;
#pragma unroll
            for (int nt = 0; nt < 8; ++nt) {
                const int h0 = wh * 64 + nt * 8 + t4 * 2;
                float2 bv = *(const float2*)(b1row + h0);
                float x = acc[mm][nt][hf * 2 + 0] + s_a1[h0] + bv.x;
                x = x > 0.f ? x : 0.01f * x;
                float y = acc[mm][nt][hf * 2 + 1] + s_a1[h0 + 1] + bv.y;
                y = y > 0.f ? y : 0.01f * y;
                s += s_u[h0] * x + s_u[h0 + 1] * y;
            }
            s += __shfl_xor_sync(0xffffffffu, s, 1);
            s += __shfl_xor_sync(0xffffffffu, s, 2);
            if (t4 == 0) sp[wh][jl] = s;
        }
    }
    __syncthreads();
    if (tid < 128) {
        float l = sp[0][tid] + sp[1][tid] + sp[2][tid] + sp[3][tid] + c0v;
        g_logits[(size_t)i * NN + jt * 128 + tid] = l;
    }
}

// ---------------------------------------------------------------------------
// Softmax + mask renorm per row
// ---------------------------------------------------------------------------
__global__ void k_conf(const float* __restrict__ mask) {
    const int i = blockIdx.x, tid = threadIdx.x;
    __shared__ float sr[256];
    float l0 = g_logits[i * NN + tid];
    float l1 = g_logits[i * NN + 256 + tid];

    sr[tid] = fmaxf(l0, l1);
    __syncthreads();
    for (int s = 128; s > 0; s >>= 1) {
        if (tid < s) sr[tid] = fmaxf(sr[tid], sr[tid + s]);
        __syncthreads();
    }
    const float m = sr[0];
    __syncthreads();

    float e0 = __expf(l0 - m), e1 = __expf(l1 - m);
    sr[tid] = e0 + e1;
    __syncthreads();
    for (int s = 128; s > 0; s >>= 1) {
        if (tid < s) sr[tid] += sr[tid + s];
        __syncthreads();
    }
    const float E = sr[0];
    __syncthreads();

    float m0 = mask[i * NN + tid], m1 = mask[i * NN + 256 + tid];
    float em0 = e0 * m0, em1 = e1 * m1;
    sr[tid] = em0 + em1;
    __syncthreads();
    for (int s = 128; s > 0; s >>= 1) {
        if (tid < s) sr[tid] += sr[tid + s];
        __syncthreads();
    }
    const float EM = sr[0];
    const float inv = 1.f / (EM + 1e-8f * E);
    g_conf[i * NN + tid] = em0 * inv;
    g_conf[i * NN + 256 + tid] = em1 * inv;
    if (tid == 0) g_ssum[i] = EM * inv;
}

// ---------------------------------------------------------------------------
// Pass 2: conv + conf-weighted j-reduce. grid (4 jt, 512 i), block 512
// ---------------------------------------------------------------------------
__global__ void __launch_bounds__(512, 1) k_pass2_m() {
    __shared__ float s_ac[256], gp[4][256];
    const int tid = threadIdx.x;
    const int lane = tid & 31, w = tid >> 5, wj = w >> 2, wh = w & 3;
    const int g = lane >> 2, t4 = lane & 3;
    const int jt = blockIdx.x, i = blockIdx.y;
    if (tid < 256) s_ac[tid] = g_Ac[i * 256 + tid];
    __syncthreads();

    float acc[2][8][4];
#pragma unroll
    for (int a = 0; a < 2; ++a)
#pragma unroll
        for (int b = 0; b < 8; ++b)
#pragma unroll
            for (int c = 0; c < 4; ++c) acc[a][b][c] = 0.f;

    mma_mainloop(acc, i, jt, wj, wh, lane, 1);

    float hs[8][2];
#pragma unroll
    for (int nt = 0; nt < 8; ++nt) { hs[nt][0] = 0.f; hs[nt][1] = 0.f; }

#pragma unroll
    for (int mm = 0; mm < 2; ++mm) {
#pragma unroll
        for (int hf = 0; hf < 2; ++hf) {
            const int jl = wj * 32 + mm * 16 + g + hf * 8;
            const int jgl = jt * 128 + jl;
            const float c = g_conf[(size_t)i * NN + jgl];
            const float* bcrow = g_Bc + (size_t)jgl * 256;
#pragma unroll
            for (int nt = 0; nt < 8; ++nt) {
                const int h0 = wh * 64 + nt * 8 + t4 * 2;
                float2 bv = *(const float2*)(bcrow + h0);
                float x = fmaxf(acc[mm][nt][hf * 2 + 0] + s_ac[h0] + bv.x, 0.f);
                float y = fmaxf(acc[mm][nt][hf * 2 + 1] + s_ac[h0 + 1] + bv.y, 0.f);
                hs[nt][0] += c * x;
                hs[nt][1] += c * y;
            }
        }
    }
#pragma unroll
    for (int nt = 0; nt < 8; ++nt) {
#pragma unroll
        for (int r = 0; r < 2; ++r) {
            float v = hs[nt][r];
            v += __shfl_xor_sync(0xffffffffu, v, 4);
            v += __shfl_xor_sync(0xffffffffu, v, 8);
            v += __shfl_xor_sync(0xffffffffu, v, 16);
            if (g == 0) gp[wj][wh * 64 + nt * 8 + t4 * 2 + r] = v;
        }
    }
    __syncthreads();
    if (tid < 256) {
        g_Gpart[((size_t)jt * NN + i) * 256 + tid] =
            gp[0][tid] + gp[1][tid] + gp[2][tid] + gp[3][tid];
    }
}

// Reduce 4 j-tile partials
__global__ void k_reduceG() {
    const int i = blockIdx.x, h = threadIdx.x;
    float s = 0.f;
#pragma unroll
    for (int c = 0; c < 4; ++c) s += g_Gpart[((size_t)c * NN + i) * HID + h];
    g_G[i * HID + h] = s;
}

// Final tiny GEMM: out[i,d] = G[i,:]·cw2[d,:] + cb2[d]*ssum[i]
__global__ void __launch_bounds__(256) k_final(const float* __restrict__ cw2,
                                               const float* __restrict__ cb2,
                                               float* __restrict__ out) {
    __shared__ float s_G[8 * 256];
    const int i0 = blockIdx.x * 8;
    const int tid = threadIdx.x;
#pragma unroll
    for (int r = 0; r < 8; ++r) s_G[r * 256 + tid] = g_G[(i0 + r) * 256 + tid];
    __syncthreads();

    const int d = tid;
    float acc[8];
#pragma unroll
    for (int r = 0; r < 8; ++r) acc[r] = 0.f;
    const float4* wr = (const float4*)(cw2 + (size_t)d * 256);
#pragma unroll 4
    for (int k4 = 0; k4 < 64; ++k4) {
        float4 w = wr[k4];
#pragma unroll
        for (int r = 0; r < 8; ++r) {
            const float* gg = s_G + r * 256 + k4 * 4;
            acc[r] += w.x * gg[0] + w.y * gg[1] + w.z * gg[2] + w.w * gg[3];
        }
    }
    const float cb = cb2[d];
#pragma unroll
    for (int r = 0; r < 8; ++r)
        out[(i0 + r) * 256 + d] = acc[r] + cb * g_ssum[i0 + r];
}

// ---------------------------------------------------------------------------
extern "C" void kernel_launch(void* const* d_in, const int* in_sizes, int n_in,
                              void* d_out, int out_size) {
    (void)in_sizes; (void)n_in; (void)out_size;
    const float* obj   = (const float*)d_in[0];
    const float* bbox  = (const float*)d_in[1];
    const float* mask  = (const float*)d_in[2];
    const float* w1    = (const float*)d_in[3];
    const float* b1    = (const float*)d_in[4];
    const float* gamma = (const float*)d_in[5];
    const float* beta  = (const float*)d_in[6];
    const float* mean  = (const float*)d_in[7];
    const float* var   = (const float*)d_in[8];
    const float* w2    = (const float*)d_in[9];
    const float* b2    = (const float*)d_in[10];
    const float* cw1   = (const float*)d_in[11];
    const float* cb1   = (const float*)d_in[12];
    const float* cw2   = (const float*)d_in[13];
    const float* cb2   = (const float*)d_in[14];
    float* out = (float*)d_out;

    k_rowmlp<<<128, 256>>>(obj, w1, b1, cw1, cb1);
    k_bfrag<<<dim3(8, 4, 2), 128>>>(w1, cw1);
    k_uc0<<<1, 256>>>(gamma, beta, mean, var, w2, b2);
    k_afrag<<<dim3(32, 512), 256>>>(bbox);
    k_pass1_m<<<dim3(4, 512), 512>>>();
    k_conf<<<512, 256>>>(mask);
    k_pass2_m<<<dim3(4, 512), 512>>>();
    k_reduceG<<<512, 256>>>();
    k_final<<<64, 256>>>(cw2, cb2, out);
}

// round 14
// speedup vs baseline: 3.5642x; 3.5642x over previous
#include <cuda_runtime.h>
#include <cuda_bf16.h>
#include <cstdint>

// ---------------------------------------------------------------------------
// PositionRelationEncodeUnit_GCN — mma.sync (split-bf16, 2-term) implementation
//
//   h[i,j,:]  = A1[i,:] + B1[j,:] + bbox[i,j,:] @ w1c^T
//   logit[i,j]= c0 + sum_h u[h]*leaky(h[i,j,h])
//   conf      = renorm(mask * softmax_j(logit))
//   g[i,j,:]  = relu(Ac[i,:] + Bc[j,:] + bbox[i,j,:] @ cw1c^T)
//   G[i,:]    = sum_j conf[i,j]*g[i,j,:]
//   out[i,:]  = G[i,:] @ cw2^T + cb2 * sum_j conf[i,j]
//
// Per-pair GEMMs on HMMA (mma.sync.m16n8k16.bf16, fp32 acc), 2-term split:
//   A@B ≈ Ahi@Bhi + Ahi@Blo   (B split exactly; error = Alo@B ~ 2^-9 rel)
// A/B operands pre-packed in gmem in the exact mma.sync per-lane fragment
// layout, so the mainloop is pure LDG.128 + HMMA.
// Block = 64 j x 256 h, 8 warps (2 wj x 4 wh), warp tile 32j x 64h.
// ---------------------------------------------------------------------------

#define NN   512
#define HID  256
#define DB   128

// ----- device scratch -----
__device__ __align__(16) float g_A1[NN * HID];
__device__ __align__(16) float g_B1[NN * HID];
__device__ __align__(16) float g_Ac[NN * HID];
__device__ __align__(16) float g_Bc[NN * HID];
__device__ float g_u[HID];
__device__ float g_c0;
__device__ __align__(16) float g_logits[NN * NN];
__device__ __align__(16) float g_conf[NN * NN];
__device__ float g_ssum[NN];
__device__ __align__(16) float g_Gpart[8 * NN * HID];
__device__ __align__(16) float g_G[NN * HID];

// A fragments (hi only): [i (512)][jm (32)][kt (8)][lane (32)] x uint4
__device__ uint4 g_Afh[NN * 32 * 8 * 32];
// B fragments: [mat (2)][prec (2)][ ((kt*4+hw)*4+np)*32 + lane ] x uint4
__device__ uint4 g_Bf[2][2][8 * 4 * 4 * 32];

// ----- helpers -----
__device__ __forceinline__ uint32_t pk2(__nv_bfloat16 a, __nv_bfloat16 b) {
    return (uint32_t)__bfloat16_as_ushort(a) |
           ((uint32_t)__bfloat16_as_ushort(b) << 16);
}
__device__ __forceinline__ void splt(float v, __nv_bfloat16& hi, __nv_bfloat16& lo) {
    hi = __float2bfloat16(v);
    lo = __float2bfloat16(v - __bfloat162float(hi));
}
__device__ __forceinline__ void mma16816(float* c, const uint32_t* a,
                                         uint32_t b0, uint32_t b1) {
    asm volatile(
        "mma.sync.aligned.m16n8k16.row.col.f32.bf16.bf16.f32 "
        "{%0,%1,%2,%3}, {%4,%5,%6,%7}, {%8,%9}, {%0,%1,%2,%3};"
        : "+f"(c[0]), "+f"(c[1]), "+f"(c[2]), "+f"(c[3])
        : "r"(a[0]), "r"(a[1]), "r"(a[2]), "r"(a[3]), "r"(b0), "r"(b1));
}

// ---------------------------------------------------------------------------
// Precompute A1/B1/Ac/Bc (object-feature halves of the first Linears)
// ---------------------------------------------------------------------------
__global__ void __launch_bounds__(256) k_rowmlp(const float* __restrict__ obj,
                                                const float* __restrict__ w1,
                                                const float* __restrict__ b1,
                                                const float* __restrict__ cw1,
                                                const float* __restrict__ cb1) {
    __shared__ float s_obj[4 * 256];
    const int i0 = blockIdx.x * 4;
    const int tid = threadIdx.x;
#pragma unroll
    for (int r = 0; r < 4; ++r) s_obj[r * 256 + tid] = obj[(i0 + r) * 256 + tid];
    __syncthreads();

    const int h = tid;
    float aA[4] = {0.f, 0.f, 0.f, 0.f}, aB[4] = {0.f, 0.f, 0.f, 0.f};
    float aC[4] = {0.f, 0.f, 0.f, 0.f}, aD[4] = {0.f, 0.f, 0.f, 0.f};
    const float4* wr = (const float4*)(w1 + (size_t)h * 640);
    const float4* cr = (const float4*)(cw1 + (size_t)h * 640);
#pragma unroll 4
    for (int k4 = 0; k4 < 64; ++k4) {
        float4 wa = wr[k4], wb = wr[64 + k4];
        float4 ca = cr[k4], cb = cr[64 + k4];
#pragma unroll
        for (int r = 0; r < 4; ++r) {
            const float* o = s_obj + r * 256 + k4 * 4;
            float o0 = o[0], o1 = o[1], o2 = o[2], o3 = o[3];
            aA[r] += wa.x * o0 + wa.y * o1 + wa.z * o2 + wa.w * o3;
            aB[r] += wb.x * o0 + wb.y * o1 + wb.z * o2 + wb.w * o3;
            aC[r] += ca.x * o0 + ca.y * o1 + ca.z * o2 + ca.w * o3;
            aD[r] += cb.x * o0 + cb.y * o1 + cb.z * o2 + cb.w * o3;
        }
    }
    const float bb1 = b1[h], bcb1 = cb1[h];
#pragma unroll
    for (int r = 0; r < 4; ++r) {
        g_A1[(i0 + r) * 256 + h] = aA[r] + bb1;
        g_B1[(i0 + r) * 256 + h] = aB[r];
        g_Ac[(i0 + r) * 256 + h] = aC[r] + bcb1;
        g_Bc[(i0 + r) * 256 + h] = aD[r];
    }
}

// Fold BN+w2 into (u, c0)
__global__ void k_uc0(const float* __restrict__ gamma, const float* __restrict__ beta,
                      const float* __restrict__ mean, const float* __restrict__ var,
                      const float* __restrict__ w2, const float* __restrict__ b2) {
    const int h = threadIdx.x;
    float rs = rsqrtf(var[h] + 1e-5f);
    float sc = gamma[h] * rs;
    g_u[h] = sc * w2[h];
    float t = (beta[h] - mean[h] * sc) * w2[h];
    __shared__ float sr[256];
    sr[h] = t;
    __syncthreads();
    for (int s = 128; s > 0; s >>= 1) {
        if (h < s) sr[h] += sr[h + s];
        __syncthreads();
    }
    if (h == 0) g_c0 = sr[0] + b2[0];
}

// ---------------------------------------------------------------------------
// B fragments. grid (8 kt, 4 hw, 2 mat), block 128 (4 np x 32 lanes)
// ---------------------------------------------------------------------------
__global__ void k_bfrag(const float* __restrict__ w1, const float* __restrict__ cw1) {
    const int kt = blockIdx.x, hw = blockIdx.y, mat = blockIdx.z;
    const int np = threadIdx.x >> 5, lane = threadIdx.x & 31;
    const int g = lane >> 2, t4 = lane & 3;
    const float* W = mat ? cw1 : w1;
    const int n0 = hw * 64 + np * 16 + g;
    const int n1 = n0 + 8;
    const int k0 = kt * 16 + t4 * 2;
    const float* r0 = W + (size_t)n0 * 640 + 512;
    const float* r1 = W + (size_t)n1 * 640 + 512;
    __nv_bfloat16 h00a, l00a, h00b, l00b, h01a, l01a, h01b, l01b;
    __nv_bfloat16 h10a, l10a, h10b, l10b, h11a, l11a, h11b, l11b;
    splt(r0[k0], h00a, l00a);     splt(r0[k0 + 1], h00b, l00b);
    splt(r0[k0 + 8], h01a, l01a); splt(r0[k0 + 9], h01b, l01b);
    splt(r1[k0], h10a, l10a);     splt(r1[k0 + 1], h10b, l10b);
    splt(r1[k0 + 8], h11a, l11a); splt(r1[k0 + 9], h11b, l11b);
    const int idx = ((kt * 4 + hw) * 4 + np) * 32 + lane;
    g_Bf[mat][0][idx] = make_uint4(pk2(h00a, h00b), pk2(h01a, h01b),
                                   pk2(h10a, h10b), pk2(h11a, h11b));
    g_Bf[mat][1][idx] = make_uint4(pk2(l00a, l00b), pk2(l01a, l01b),
                                   pk2(l10a, l10b), pk2(l11a, l11b));
}

// ---------------------------------------------------------------------------
// A fragments (hi only). grid (32 jm, 512 i), block 256 (8 kt x 32 lanes)
// ---------------------------------------------------------------------------
__global__ void __launch_bounds__(256) k_afrag(const float* __restrict__ bbox) {
    const int kt = threadIdx.x >> 5, lane = threadIdx.x & 31;
    const int jm = blockIdx.x, i = blockIdx.y;
    const int g = lane >> 2, t4 = lane & 3;
    const float* base = bbox + ((size_t)i * NN + (size_t)jm * 16) * DB;
    const int c0 = kt * 16 + t4 * 2;
    float2 v00 = *(const float2*)(base + (size_t)g * DB + c0);
    float2 v01 = *(const float2*)(base + (size_t)g * DB + c0 + 8);
    float2 v10 = *(const float2*)(base + (size_t)(g + 8) * DB + c0);
    float2 v11 = *(const float2*)(base + (size_t)(g + 8) * DB + c0 + 8);
    const size_t idx = (((size_t)i * 32 + jm) * 8 + kt) * 32 + lane;
    g_Afh[idx] = make_uint4(
        pk2(__float2bfloat16(v00.x), __float2bfloat16(v00.y)),
        pk2(__float2bfloat16(v10.x), __float2bfloat16(v10.y)),
        pk2(__float2bfloat16(v01.x), __float2bfloat16(v01.y)),
        pk2(__float2bfloat16(v11.x), __float2bfloat16(v11.y)));
}

// ---------------------------------------------------------------------------
// Tensor mainloop: acc[2 mm][8 nt][4]; warp tile 32j x 64h, virtual K=256
// A loaded once per kt, used against Bhi and Blo.
// ---------------------------------------------------------------------------
__device__ __forceinline__ void mma_mainloop(float acc[2][8][4], int i, int jm0,
                                             int wh, int lane, int mat) {
    const uint4* pa0 = g_Afh + (((size_t)i * 32 + jm0) * 8) * 32 + lane;
    const uint4* pa1 = pa0 + 8 * 32;
    const uint4* pbh = g_Bf[mat][0] + wh * 128 + lane;
    const uint4* pbl = g_Bf[mat][1] + wh * 128 + lane;
#pragma unroll 2
    for (int kt = 0; kt < 8; ++kt) {
        uint4 a0 = pa0[kt * 32];
        uint4 a1 = pa1[kt * 32];
#pragma unroll
        for (int np = 0; np < 4; ++np) {
            uint4 bq = pbh[kt * 512 + np * 32];
            mma16816(acc[0][np * 2 + 0], (const uint32_t*)&a0, bq.x, bq.y);
            mma16816(acc[1][np * 2 + 0], (const uint32_t*)&a1, bq.x, bq.y);
            mma16816(acc[0][np * 2 + 1], (const uint32_t*)&a0, bq.z, bq.w);
            mma16816(acc[1][np * 2 + 1], (const uint32_t*)&a1, bq.z, bq.w);
        }
#pragma unroll
        for (int np = 0; np < 4; ++np) {
            uint4 bq = pbl[kt * 512 + np * 32];
            mma16816(acc[0][np * 2 + 0], (const uint32_t*)&a0, bq.x, bq.y);
            mma16816(acc[1][np * 2 + 0], (const uint32_t*)&a1, bq.x, bq.y);
            mma16816(acc[0][np * 2 + 1], (const uint32_t*)&a0, bq.z, bq.w);
            mma16816(acc[1][np * 2 + 1], (const uint32_t*)&a1, bq.z, bq.w);
        }
    }
}

// ---------------------------------------------------------------------------
// Pass 1: logits. grid (8 jt, 512 i), block 256 (2 wj x 4 wh warps)
// ---------------------------------------------------------------------------
__global__ void __launch_bounds__(256, 2) k_pass1_m() {
    __shared__ float s_u[256], s_a1[256], sp[4][64];
    const int tid = threadIdx.x;
    const int lane = tid & 31, w = tid >> 5, wj = w >> 2, wh = w & 3;
    const int g = lane >> 2, t4 = lane & 3;
    const int jt = blockIdx.x, i = blockIdx.y;
    s_u[tid] = g_u[tid];
    s_a1[tid] = g_A1[i * 256 + tid];
    __syncthreads();

    float acc[2][8][4];
#pragma unroll
    for (int a = 0; a < 2; ++a)
#pragma unroll
        for (int b = 0; b < 8; ++b)
#pragma unroll
            for (int c = 0; c < 4; ++c) acc[a][b][c] = 0.f;

    mma_mainloop(acc, i, jt * 4 + wj * 2, wh, lane, 0);

    const float c0v = g_c0;
#pragma unroll
    for (int mm = 0; mm < 2; ++mm) {
#pragma unroll
        for (int hf = 0; hf < 2; ++hf) {
            const int jl = wj * 32 + mm * 16 + g + hf * 8;     // 0..63
            const int jgl = jt * 64 + jl;
            const float* b1row = g_B1 + (size_t)jgl * 256;
            float s = 0.f;
#pragma unroll
            for (int nt = 0; nt < 8; ++nt) {
                const int h0 = wh * 64 + nt * 8 + t4 * 2;
                float2 bv = *(const float2*)(b1row + h0);
                float x = acc[mm][nt][hf * 2 + 0] + s_a1[h0] + bv.x;
                x = x > 0.f ? x : 0.01f * x;
                float y = acc[mm][nt][hf * 2 + 1] + s_a1[h0 + 1] + bv.y;
                y = y > 0.f ? y : 0.01f * y;
                s += s_u[h0] * x + s_u[h0 + 1] * y;
            }
            s += __shfl_xor_sync(0xffffffffu, s, 1);
            s += __shfl_xor_sync(0xffffffffu, s, 2);
            if (t4 == 0) sp[wh][jl] = s;
        }
    }
    __syncthreads();
    if (tid < 64) {
        float l = sp[0][tid] + sp[1][tid] + sp[2][tid] + sp[3][tid] + c0v;
        g_logits[(size_t)i * NN + jt * 64 + tid] = l;
    }
}

// ---------------------------------------------------------------------------
// Softmax + mask renorm per row
// ---------------------------------------------------------------------------
__global__ void k_conf(const float* __restrict__ mask) {
    const int i = blockIdx.x, tid = threadIdx.x;
    __shared__ float sr[256];
    float l0 = g_logits[i * NN + tid];
    float l1 = g_logits[i * NN + 256 + tid];

    sr[tid] = fmaxf(l0, l1);
    __syncthreads();
    for (int s = 128; s > 0; s >>= 1) {
        if (tid < s) sr[tid] = fmaxf(sr[tid], sr[tid + s]);
        __syncthreads();
    }
    const float m = sr[0];
    __syncthreads();

    float e0 = __expf(l0 - m), e1 = __expf(l1 - m);
    sr[tid] = e0 + e1;
    __syncthreads();
    for (int s = 128; s > 0; s >>= 1) {
        if (tid < s) sr[tid] += sr[tid + s];
        __syncthreads();
    }
    const float E = sr[0];
    __syncthreads();

    float m0 = mask[i * NN + tid], m1 = mask[i * NN + 256 + tid];
    float em0 = e0 * m0, em1 = e1 * m1;
    sr[tid] = em0 + em1;
    __syncthreads();
    for (int s = 128; s > 0; s >>= 1) {
        if (tid < s) sr[tid] += sr[tid + s];
        __syncthreads();
    }
    const float EM = sr[0];
    const float inv = 1.f / (EM + 1e-8f * E);
    g_conf[i * NN + tid] = em0 * inv;
    g_conf[i * NN + 256 + tid] = em1 * inv;
    if (tid == 0) g_ssum[i] = EM * inv;
}

// ---------------------------------------------------------------------------
// Pass 2: conv + conf-weighted j-reduce. grid (8 jt, 512 i), block 256
// ---------------------------------------------------------------------------
__global__ void __launch_bounds__(256, 2) k_pass2_m() {
    __shared__ float s_ac[256], gp[2][256];
    const int tid = threadIdx.x;
    const int lane = tid & 31, w = tid >> 5, wj = w >> 2, wh = w & 3;
    const int g = lane >> 2, t4 = lane & 3;
    const int jt = blockIdx.x, i = blockIdx.y;
    s_ac[tid] = g_Ac[i * 256 + tid];
    __syncthreads();

    float acc[2][8][4];
#pragma unroll
    for (int a = 0; a < 2; ++a)
#pragma unroll
        for (int b = 0; b < 8; ++b)
#pragma unroll
            for (int c = 0; c < 4; ++c) acc[a][b][c] = 0.f;

    mma_mainloop(acc, i, jt * 4 + wj * 2, wh, lane, 1);

    float hs[8][2];
#pragma unroll
    for (int nt = 0; nt < 8; ++nt) { hs[nt][0] = 0.f; hs[nt][1] = 0.f; }

#pragma unroll
    for (int mm = 0; mm < 2; ++mm) {
#pragma unroll
        for (int hf = 0; hf < 2; ++hf) {
            const int jl = wj * 32 + mm * 16 + g + hf * 8;
            const int jgl = jt * 64 + jl;
            const float c = g_conf[(size_t)i * NN + jgl];
            const float* bcrow = g_Bc + (size_t)jgl * 256;
#pragma unroll
            for (int nt = 0; nt < 8; ++nt) {
                const int h0 = wh * 64 + nt * 8 + t4 * 2;
                float2 bv = *(const float2*)(bcrow + h0);
                float x = fmaxf(acc[mm][nt][hf * 2 + 0] + s_ac[h0] + bv.x, 0.f);
                float y = fmaxf(acc[mm][nt][hf * 2 + 1] + s_ac[h0 + 1] + bv.y, 0.f);
                hs[nt][0] += c * x;
                hs[nt][1] += c * y;
            }
        }
    }
#pragma unroll
    for (int nt = 0; nt < 8; ++nt) {
#pragma unroll
        for (int r = 0; r < 2; ++r) {
            float v = hs[nt][r];
            v += __shfl_xor_sync(0xffffffffu, v, 4);
            v += __shfl_xor_sync(0xffffffffu, v, 8);
            v += __shfl_xor_sync(0xffffffffu, v, 16);
            if (g == 0) gp[wj][wh * 64 + nt * 8 + t4 * 2 + r] = v;
        }
    }
    __syncthreads();
    g_Gpart[((size_t)jt * NN + i) * 256 + tid] = gp[0][tid] + gp[1][tid];
}

// Reduce 8 j-tile partials
__global__ void k_reduceG() {
    const int i = blockIdx.x, h = threadIdx.x;
    float s = 0.f;
#pragma unroll
    for (int c = 0; c < 8; ++c) s += g_Gpart[((size_t)c * NN + i) * HID + h];
    g_G[i * HID + h] = s;
}

// Final tiny GEMM: out[i,d] = G[i,:]·cw2[d,:] + cb2[d]*ssum[i]
__global__ void __launch_bounds__(256) k_final(const float* __restrict__ cw2,
                                               const float* __restrict__ cb2,
                                               float* __restrict__ out) {
    __shared__ float s_G[8 * 256];
    const int i0 = blockIdx.x * 8;
    const int tid = threadIdx.x;
#pragma unroll
    for (int r = 0; r < 8; ++r) s_G[r * 256 + tid] = g_G[(i0 + r) * 256 + tid];
    __syncthreads();

    const int d = tid;
    float acc[8];
#pragma unroll
    for (int r = 0; r < 8; ++r) acc[r] = 0.f;
    const float4* wr = (const float4*)(cw2 + (size_t)d * 256);
#pragma unroll 4
    for (int k4 = 0; k4 < 64; ++k4) {
        float4 w = wr[k4];
#pragma unroll
        for (int r = 0; r < 8; ++r) {
            const float* gg = s_G + r * 256 + k4 * 4;
            acc[r] += w.x * gg[0] + w.y * gg[1] + w.z * gg[2] + w.w * gg[3];
        }
    }
    const float cb = cb2[d];
#pragma unroll
    for (int r = 0; r < 8; ++r)
        out[(i0 + r) * 256 + d] = acc[r] + cb * g_ssum[i0 + r];
}

// ---------------------------------------------------------------------------
extern "C" void kernel_launch(void* const* d_in, const int* in_sizes, int n_in,
                              void* d_out, int out_size) {
    (void)in_sizes; (void)n_in; (void)out_size;
    const float* obj   = (const float*)d_in[0];
    const float* bbox  = (const float*)d_in[1];
    const float* mask  = (const float*)d_in[2];
    const float* w1    = (const float*)d_in[3];
    const float* b1    = (const float*)d_in[4];
    const float* gamma = (const float*)d_in[5];
    const float* beta  = (const float*)d_in[6];
    const float* mean  = (const float*)d_in[7];
    const float* var   = (const float*)d_in[8];
    const float* w2    = (const float*)d_in[9];
    const float* b2    = (const float*)d_in[10];
    const float* cw1   = (const float*)d_in[11];
    const float* cb1   = (const float*)d_in[12];
    const float* cw2   = (const float*)d_in[13];
    const float* cb2   = (const float*)d_in[14];
    float* out = (float*)d_out;

    k_rowmlp<<<128, 256>>>(obj, w1, b1, cw1, cb1);
    k_bfrag<<<dim3(8, 4, 2), 128>>>(w1, cw1);
    k_uc0<<<1, 256>>>(gamma, beta, mean, var, w2, b2);
    k_afrag<<<dim3(32, 512), 256>>>(bbox);
    k_pass1_m<<<dim3(8, 512), 256>>>();
    k_conf<<<512, 256>>>(mask);
    k_pass2_m<<<dim3(8, 512), 256>>>();
    k_reduceG<<<512, 256>>>();
    k_final<<<64, 256>>>(cw2, cb2, out);
}

// round 15
// speedup vs baseline: 3.7986x; 1.0658x over previous
#include <cuda_runtime.h>
#include <cuda_bf16.h>
#include <cstdint>

// ---------------------------------------------------------------------------
// PositionRelationEncodeUnit_GCN — mma.sync (split-bf16, 2-term) implementation
//
//   h[i,j,:]  = A1[i,:] + B1[j,:] + bbox[i,j,:] @ w1c^T
//   logit[i,j]= c0 + sum_h u[h]*leaky(h[i,j,h])
//   conf      = renorm(mask * softmax_j(logit))
//   g[i,j,:]  = relu(Ac[i,:] + Bc[j,:] + bbox[i,j,:] @ cw1c^T)
//   G[i,:]    = sum_j conf[i,j]*g[i,j,:]
//   out[i,:]  = G[i,:] @ cw2^T + cb2 * sum_j conf[i,j]
//
// Per-pair GEMMs on HMMA (mma.sync.m16n8k16.bf16, fp32 acc), 2-term split:
//   A@B ≈ Ahi@Bhi + Ahi@Blo   (B split exactly; error = Alo@B ~ 2^-9 rel)
// Mainloop is software-pipelined: all B loads batched at top of each kt,
// next kt's A prefetched between the hi and lo MMA groups.
// Block = 64 j x 256 h, 8 warps (2 wj x 4 wh), warp tile 32j x 64h.
// ---------------------------------------------------------------------------

#define NN   512
#define HID  256
#define DB   128

// ----- device scratch -----
__device__ __align__(16) float g_A1[NN * HID];
__device__ __align__(16) float g_B1[NN * HID];
__device__ __align__(16) float g_Ac[NN * HID];
__device__ __align__(16) float g_Bc[NN * HID];
__device__ float g_u[HID];
__device__ float g_c0;
__device__ __align__(16) float g_logits[NN * NN];
__device__ __align__(16) float g_conf[NN * NN];
__device__ float g_ssum[NN];
__device__ __align__(16) float g_Gpart[8 * NN * HID];

// A fragments (hi only): [i (512)][jm (32)][kt (8)][lane (32)] x uint4
__device__ uint4 g_Afh[NN * 32 * 8 * 32];
// B fragments: [mat (2)][prec (2)][ ((kt*4+hw)*4+np)*32 + lane ] x uint4
__device__ uint4 g_Bf[2][2][8 * 4 * 4 * 32];

// ----- helpers -----
__device__ __forceinline__ uint32_t pk2(__nv_bfloat16 a, __nv_bfloat16 b) {
    return (uint32_t)__bfloat16_as_ushort(a) |
           ((uint32_t)__bfloat16_as_ushort(b) << 16);
}
__device__ __forceinline__ void splt(float v, __nv_bfloat16& hi, __nv_bfloat16& lo) {
    hi = __float2bfloat16(v);
    lo = __float2bfloat16(v - __bfloat162float(hi));
}
__device__ __forceinline__ void mma16816(float* c, const uint4& a,
                                         uint32_t b0, uint32_t b1) {
    asm volatile(
        "mma.sync.aligned.m16n8k16.row.col.f32.bf16.bf16.f32 "
        "{%0,%1,%2,%3}, {%4,%5,%6,%7}, {%8,%9}, {%0,%1,%2,%3};"
        : "+f"(c[0]), "+f"(c[1]), "+f"(c[2]), "+f"(c[3])
        : "r"(a.x), "r"(a.y), "r"(a.z), "r"(a.w), "r"(b0), "r"(b1));
}

// ---------------------------------------------------------------------------
// Precompute A1/B1/Ac/Bc (object-feature halves of the first Linears)
// ---------------------------------------------------------------------------
__global__ void __launch_bounds__(256) k_rowmlp(const float* __restrict__ obj,
                                                const float* __restrict__ w1,
                                                const float* __restrict__ b1,
                                                const float* __restrict__ cw1,
                                                const float* __restrict__ cb1) {
    __shared__ float s_obj[4 * 256];
    const int i0 = blockIdx.x * 4;
    const int tid = threadIdx.x;
#pragma unroll
    for (int r = 0; r < 4; ++r) s_obj[r * 256 + tid] = obj[(i0 + r) * 256 + tid];
    __syncthreads();

    const int h = tid;
    float aA[4] = {0.f, 0.f, 0.f, 0.f}, aB[4] = {0.f, 0.f, 0.f, 0.f};
    float aC[4] = {0.f, 0.f, 0.f, 0.f}, aD[4] = {0.f, 0.f, 0.f, 0.f};
    const float4* wr = (const float4*)(w1 + (size_t)h * 640);
    const float4* cr = (const float4*)(cw1 + (size_t)h * 640);
#pragma unroll 4
    for (int k4 = 0; k4 < 64; ++k4) {
        float4 wa = wr[k4], wb = wr[64 + k4];
        float4 ca = cr[k4], cb = cr[64 + k4];
#pragma unroll
        for (int r = 0; r < 4; ++r) {
            const float* o = s_obj + r * 256 + k4 * 4;
            float o0 = o[0], o1 = o[1], o2 = o[2], o3 = o[3];
            aA[r] += wa.x * o0 + wa.y * o1 + wa.z * o2 + wa.w * o3;
            aB[r] += wb.x * o0 + wb.y * o1 + wb.z * o2 + wb.w * o3;
            aC[r] += ca.x * o0 + ca.y * o1 + ca.z * o2 + ca.w * o3;
            aD[r] += cb.x * o0 + cb.y * o1 + cb.z * o2 + cb.w * o3;
        }
    }
    const float bb1 = b1[h], bcb1 = cb1[h];
#pragma unroll
    for (int r = 0; r < 4; ++r) {
        g_A1[(i0 + r) * 256 + h] = aA[r] + bb1;
        g_B1[(i0 + r) * 256 + h] = aB[r];
        g_Ac[(i0 + r) * 256 + h] = aC[r] + bcb1;
        g_Bc[(i0 + r) * 256 + h] = aD[r];
    }
}

// Fold BN+w2 into (u, c0)
__global__ void k_uc0(const float* __restrict__ gamma, const float* __restrict__ beta,
                      const float* __restrict__ mean, const float* __restrict__ var,
                      const float* __restrict__ w2, const float* __restrict__ b2) {
    const int h = threadIdx.x;
    float rs = rsqrtf(var[h] + 1e-5f);
    float sc = gamma[h] * rs;
    g_u[h] = sc * w2[h];
    float t = (beta[h] - mean[h] * sc) * w2[h];
    __shared__ float sr[256];
    sr[h] = t;
    __syncthreads();
    for (int s = 128; s > 0; s >>= 1) {
        if (h < s) sr[h] += sr[h + s];
        __syncthreads();
    }
    if (h == 0) g_c0 = sr[0] + b2[0];
}

// ---------------------------------------------------------------------------
// B fragments. grid (8 kt, 4 hw, 2 mat), block 128 (4 np x 32 lanes)
// ---------------------------------------------------------------------------
__global__ void k_bfrag(const float* __restrict__ w1, const float* __restrict__ cw1) {
    const int kt = blockIdx.x, hw = blockIdx.y, mat = blockIdx.z;
    const int np = threadIdx.x >> 5, lane = threadIdx.x & 31;
    const int g = lane >> 2, t4 = lane & 3;
    const float* W = mat ? cw1 : w1;
    const int n0 = hw * 64 + np * 16 + g;
    const int n1 = n0 + 8;
    const int k0 = kt * 16 + t4 * 2;
    const float* r0 = W + (size_t)n0 * 640 + 512;
    const float* r1 = W + (size_t)n1 * 640 + 512;
    __nv_bfloat16 h00a, l00a, h00b, l00b, h01a, l01a, h01b, l01b;
    __nv_bfloat16 h10a, l10a, h10b, l10b, h11a, l11a, h11b, l11b;
    splt(r0[k0], h00a, l00a);     splt(r0[k0 + 1], h00b, l00b);
    splt(r0[k0 + 8], h01a, l01a); splt(r0[k0 + 9], h01b, l01b);
    splt(r1[k0], h10a, l10a);     splt(r1[k0 + 1], h10b, l10b);
    splt(r1[k0 + 8], h11a, l11a); splt(r1[k0 + 9], h11b, l11b);
    const int idx = ((kt * 4 + hw) * 4 + np) * 32 + lane;
    g_Bf[mat][0][idx] = make_uint4(pk2(h00a, h00b), pk2(h01a, h01b),
                                   pk2(h10a, h10b), pk2(h11a, h11b));
    g_Bf[mat][1][idx] = make_uint4(pk2(l00a, l00b), pk2(l01a, l01b),
                                   pk2(l10a, l10b), pk2(l11a, l11b));
}

// ---------------------------------------------------------------------------
// A fragments (hi only). grid (32 jm, 512 i), block 256 (8 kt x 32 lanes)
// ---------------------------------------------------------------------------
__global__ void __launch_bounds__(256) k_afrag(const float* __restrict__ bbox) {
    const int kt = threadIdx.x >> 5, lane = threadIdx.x & 31;
    const int jm = blockIdx.x, i = blockIdx.y;
    const int g = lane >> 2, t4 = lane & 3;
    const float* base = bbox + ((size_t)i * NN + (size_t)jm * 16) * DB;
    const int c0 = kt * 16 + t4 * 2;
    float2 v00 = *(const float2*)(base + (size_t)g * DB + c0);
    float2 v01 = *(const float2*)(base + (size_t)g * DB + c0 + 8);
    float2 v10 = *(const float2*)(base + (size_t)(g + 8) * DB + c0);
    float2 v11 = *(const float2*)(base + (size_t)(g + 8) * DB + c0 + 8);
    const size_t idx = (((size_t)i * 32 + jm) * 8 + kt) * 32 + lane;
    g_Afh[idx] = make_uint4(
        pk2(__float2bfloat16(v00.x), __float2bfloat16(v00.y)),
        pk2(__float2bfloat16(v10.x), __float2bfloat16(v10.y)),
        pk2(__float2bfloat16(v01.x), __float2bfloat16(v01.y)),
        pk2(__float2bfloat16(v11.x), __float2bfloat16(v11.y)));
}

// ---------------------------------------------------------------------------
// Software-pipelined tensor mainloop: acc[2 mm][8 nt][4]
// Warp tile 32j x 64h, virtual K=256 (Bhi then Blo per kt).
// Per kt: batch-load 8 B quads (MLP), prefetch next A between hi/lo groups.
// ---------------------------------------------------------------------------
__device__ __forceinline__ void mma_mainloop(float acc[2][8][4], int i, int jm0,
                                             int wh, int lane, int mat) {
    const uint4* pa0 = g_Afh + (((size_t)i * 32 + jm0) * 8) * 32 + lane;
    const uint4* pa1 = pa0 + 8 * 32;
    const uint4* pbh = g_Bf[mat][0] + wh * 128 + lane;
    const uint4* pbl = g_Bf[mat][1] + wh * 128 + lane;

    uint4 a0 = pa0[0];
    uint4 a1 = pa1[0];

#pragma unroll
    for (int kt = 0; kt < 8; ++kt) {
        // batch all B loads for this kt (independent, MLP=8)
        uint4 bh0 = pbh[kt * 512 + 0];
        uint4 bh1 = pbh[kt * 512 + 32];
        uint4 bh2 = pbh[kt * 512 + 64];
        uint4 bh3 = pbh[kt * 512 + 96];
        uint4 bl0 = pbl[kt * 512 + 0];
        uint4 bl1 = pbl[kt * 512 + 32];
        uint4 bl2 = pbl[kt * 512 + 64];
        uint4 bl3 = pbl[kt * 512 + 96];

        // hi-term MMAs (16 independent accumulators)
        mma16816(acc[0][0], a0, bh0.x, bh0.y);
        mma16816(acc[1][0], a1, bh0.x, bh0.y);
        mma16816(acc[0][1], a0, bh0.z, bh0.w);
        mma16816(acc[1][1], a1, bh0.z, bh0.w);
        mma16816(acc[0][2], a0, bh1.x, bh1.y);
        mma16816(acc[1][2], a1, bh1.x, bh1.y);
        mma16816(acc[0][3], a0, bh1.z, bh1.w);
        mma16816(acc[1][3], a1, bh1.z, bh1.w);
        mma16816(acc[0][4], a0, bh2.x, bh2.y);
        mma16816(acc[1][4], a1, bh2.x, bh2.y);
        mma16816(acc[0][5], a0, bh2.z, bh2.w);
        mma16816(acc[1][5], a1, bh2.z, bh2.w);
        mma16816(acc[0][6], a0, bh3.x, bh3.y);
        mma16816(acc[1][6], a1, bh3.x, bh3.y);
        mma16816(acc[0][7], a0, bh3.z, bh3.w);
        mma16816(acc[1][7], a1, bh3.z, bh3.w);

        // prefetch next kt's A while lo MMAs run
        uint4 a0n = a0, a1n = a1;
        if (kt < 7) {
            a0n = pa0[(kt + 1) * 32];
            a1n = pa1[(kt + 1) * 32];
        }

        // lo-term MMAs
        mma16816(acc[0][0], a0, bl0.x, bl0.y);
        mma16816(acc[1][0], a1, bl0.x, bl0.y);
        mma16816(acc[0][1], a0, bl0.z, bl0.w);
        mma16816(acc[1][1], a1, bl0.z, bl0.w);
        mma16816(acc[0][2], a0, bl1.x, bl1.y);
        mma16816(acc[1][2], a1, bl1.x, bl1.y);
        mma16816(acc[0][3], a0, bl1.z, bl1.w);
        mma16816(acc[1][3], a1, bl1.z, bl1.w);
        mma16816(acc[0][4], a0, bl2.x, bl2.y);
        mma16816(acc[1][4], a1, bl2.x, bl2.y);
        mma16816(acc[0][5], a0, bl2.z, bl2.w);
        mma16816(acc[1][5], a1, bl2.z, bl2.w);
        mma16816(acc[0][6], a0, bl3.x, bl3.y);
        mma16816(acc[1][6], a1, bl3.x, bl3.y);
        mma16816(acc[0][7], a0, bl3.z, bl3.w);
        mma16816(acc[1][7], a1, bl3.z, bl3.w);

        a0 = a0n;
        a1 = a1n;
    }
}

// ---------------------------------------------------------------------------
// Pass 1: logits. grid (8 jt, 512 i), block 256 (2 wj x 4 wh warps)
// ---------------------------------------------------------------------------
__global__ void __launch_bounds__(256, 2) k_pass1_m() {
    __shared__ float s_u[256], s_a1[256], sp[4][64];
    const int tid = threadIdx.x;
    const int lane = tid & 31, w = tid >> 5, wj = w >> 2, wh = w & 3;
    const int g = lane >> 2, t4 = lane & 3;
    const int jt = blockIdx.x, i = blockIdx.y;
    s_u[tid] = g_u[tid];
    s_a1[tid] = g_A1[i * 256 + tid];
    __syncthreads();

    float acc[2][8][4];
#pragma unroll
    for (int a = 0; a < 2; ++a)
#pragma unroll
        for (int b = 0; b < 8; ++b)
#pragma unroll
            for (int c = 0; c < 4; ++c) acc[a][b][c] = 0.f;

    mma_mainloop(acc, i, jt * 4 + wj * 2, wh, lane, 0);

    const float c0v = g_c0;
#pragma unroll
    for (int mm = 0; mm < 2; ++mm) {
#pragma unroll
        for (int hf = 0; hf < 2; ++hf) {
            const int jl = wj * 32 + mm * 16 + g + hf * 8;     // 0..63
            const int jgl = jt * 64 + jl;
            const float* b1row = g_B1 + (size_t)jgl * 256;
            float s = 0.f;
#pragma unroll
            for (int nt = 0; nt < 8; ++nt) {
                const int h0 = wh * 64 + nt * 8 + t4 * 2;
                float2 bv = *(const float2*)(b1row + h0);
                float x = acc[mm][nt][hf * 2 + 0] + s_a1[h0] + bv.x;
                x = x > 0.f ? x : 0.01f * x;
                float y = acc[mm][nt][hf * 2 + 1] + s_a1[h0 + 1] + bv.y;
                y = y > 0.f ? y : 0.01f * y;
                s += s_u[h0] * x + s_u[h0 + 1] * y;
            }
            s += __shfl_xor_sync(0xffffffffu, s, 1);
            s += __shfl_xor_sync(0xffffffffu, s, 2);
            if (t4 == 0) sp[wh][jl] = s;
        }
    }
    __syncthreads();
    if (tid < 64) {
        float l = sp[0][tid] + sp[1][tid] + sp[2][tid] + sp[3][tid] + c0v;
        g_logits[(size_t)i * NN + jt * 64 + tid] = l;
    }
}

// ---------------------------------------------------------------------------
// Softmax + mask renorm: one warp per row, shfl-only. grid 64, block 256.
// ---------------------------------------------------------------------------
__global__ void __launch_bounds__(256) k_conf(const float* __restrict__ mask) {
    const int w = threadIdx.x >> 5, lane = threadIdx.x & 31;
    const int i = blockIdx.x * 8 + w;

    const float4* Lr = (const float4*)(g_logits + (size_t)i * NN) + lane * 4;
    float4 v0 = Lr[0], v1 = Lr[1], v2 = Lr[2], v3 = Lr[3];

    float m = fmaxf(fmaxf(fmaxf(v0.x, v0.y), fmaxf(v0.z, v0.w)),
                    fmaxf(fmaxf(v1.x, v1.y), fmaxf(v1.z, v1.w)));
    m = fmaxf(m, fmaxf(fmaxf(fmaxf(v2.x, v2.y), fmaxf(v2.z, v2.w)),
                       fmaxf(fmaxf(v3.x, v3.y), fmaxf(v3.z, v3.w))));
#pragma unroll
    for (int off = 16; off > 0; off >>= 1)
        m = fmaxf(m, __shfl_xor_sync(0xffffffffu, m, off));

    float e[16];
    e[0] = __expf(v0.x - m);  e[1] = __expf(v0.y - m);
    e[2] = __expf(v0.z - m);  e[3] = __expf(v0.w - m);
    e[4] = __expf(v1.x - m);  e[5] = __expf(v1.y - m);
    e[6] = __expf(v1.z - m);  e[7] = __expf(v1.w - m);
    e[8] = __expf(v2.x - m);  e[9] = __expf(v2.y - m);
    e[10] = __expf(v2.z - m); e[11] = __expf(v2.w - m);
    e[12] = __expf(v3.x - m); e[13] = __expf(v3.y - m);
    e[14] = __expf(v3.z - m); e[15] = __expf(v3.w - m);

    float E = 0.f;
#pragma unroll
    for (int q = 0; q < 16; ++q) E += e[q];
#pragma unroll
    for (int off = 16; off > 0; off >>= 1)
        E += __shfl_xor_sync(0xffffffffu, E, off);

    const float4* Mr = (const float4*)(mask + (size_t)i * NN) + lane * 4;
    float em[16];
    float EM = 0.f;
#pragma unroll
    for (int q4 = 0; q4 < 4; ++q4) {
        float4 mv = Mr[q4];
        em[q4 * 4 + 0] = e[q4 * 4 + 0] * mv.x;
        em[q4 * 4 + 1] = e[q4 * 4 + 1] * mv.y;
        em[q4 * 4 + 2] = e[q4 * 4 + 2] * mv.z;
        em[q4 * 4 + 3] = e[q4 * 4 + 3] * mv.w;
        EM += em[q4 * 4 + 0] + em[q4 * 4 + 1] + em[q4 * 4 + 2] + em[q4 * 4 + 3];
    }
#pragma unroll
    for (int off = 16; off > 0; off >>= 1)
        EM += __shfl_xor_sync(0xffffffffu, EM, off);

    const float inv = 1.f / (EM + 1e-8f * E);
    float4* Cw = (float4*)(g_conf + (size_t)i * NN) + lane * 4;
#pragma unroll
    for (int q4 = 0; q4 < 4; ++q4)
        Cw[q4] = make_float4(em[q4 * 4 + 0] * inv, em[q4 * 4 + 1] * inv,
                             em[q4 * 4 + 2] * inv, em[q4 * 4 + 3] * inv);
    if (lane == 0) g_ssum[i] = EM * inv;
}

// ---------------------------------------------------------------------------
// Pass 2: conv + conf-weighted j-reduce. grid (8 jt, 512 i), block 256
// ---------------------------------------------------------------------------
__global__ void __launch_bounds__(256, 2) k_pass2_m() {
    __shared__ float s_ac[256], gp[2][256];
    const int tid = threadIdx.x;
    const int lane = tid & 31, w = tid >> 5, wj = w >> 2, wh = w & 3;
    const int g = lane >> 2, t4 = lane & 3;
    const int jt = blockIdx.x, i = blockIdx.y;
    s_ac[tid] = g_Ac[i * 256 + tid];
    __syncthreads();

    float acc[2][8][4];
#pragma unroll
    for (int a = 0; a < 2; ++a)
#pragma unroll
        for (int b = 0; b < 8; ++b)
#pragma unroll
            for (int c = 0; c < 4; ++c) acc[a][b][c] = 0.f;

    mma_mainloop(acc, i, jt * 4 + wj * 2, wh, lane, 1);

    float hs[8][2];
#pragma unroll
    for (int nt = 0; nt < 8; ++nt) { hs[nt][0] = 0.f; hs[nt][1] = 0.f; }

#pragma unroll
    for (int mm = 0; mm < 2; ++mm) {
#pragma unroll
        for (int hf = 0; hf < 2; ++hf) {
            const int jl = wj * 32 + mm * 16 + g + hf * 8;
            const int jgl = jt * 64 + jl;
            const float c = g_conf[(size_t)i * NN + jgl];
            const float* bcrow = g_Bc + (size_t)jgl * 256;
#pragma unroll
            for (int nt = 0; nt < 8; ++nt) {
                const int h0 = wh * 64 + nt * 8 + t4 * 2;
                float2 bv = *(const float2*)(bcrow + h0);
                float x = fmaxf(acc[mm][nt][hf * 2 + 0] + s_ac[h0] + bv.x, 0.f);
                float y = fmaxf(acc[mm][nt][hf * 2 + 1] + s_ac[h0 + 1] + bv.y, 0.f);
                hs[nt][0] += c * x;
                hs[nt][1] += c * y;
            }
        }
    }
#pragma unroll
    for (int nt = 0; nt < 8; ++nt) {
#pragma unroll
        for (int r = 0; r < 2; ++r) {
            float v = hs[nt][r];
            v += __shfl_xor_sync(0xffffffffu, v, 4);
            v += __shfl_xor_sync(0xffffffffu, v, 8);
            v += __shfl_xor_sync(0xffffffffu, v, 16);
            if (g == 0) gp[wj][wh * 64 + nt * 8 + t4 * 2 + r] = v;
        }
    }
    __syncthreads();
    g_Gpart[((size_t)jt * NN + i) * 256 + tid] = gp[0][tid] + gp[1][tid];
}

// ---------------------------------------------------------------------------
// Final: reduce 8 j-tile partials + tiny GEMM.
// out[i,d] = (sum_c Gpart[c,i,:])·cw2[d,:] + cb2[d]*ssum[i]. grid 64 (8 i each)
// ---------------------------------------------------------------------------
__global__ void __launch_bounds__(256) k_final(const float* __restrict__ cw2,
                                               const float* __restrict__ cb2,
                                               float* __restrict__ out) {
    __shared__ float s_G[8 * 256];
    const int i0 = blockIdx.x * 8;
    const int tid = threadIdx.x;
#pragma unroll
    for (int r = 0; r < 8; ++r) {
        float s = 0.f;
#pragma unroll
        for (int c = 0; c < 8; ++c)
            s += g_Gpart[((size_t)c * NN + (i0 + r)) * 256 + tid];
        s_G[r * 256 + tid] = s;
    }
    __syncthreads();

    const int d = tid;
    float acc[8];
#pragma unroll
    for (int r = 0; r < 8; ++r) acc[r] = 0.f;
    const float4* wr = (const float4*)(cw2 + (size_t)d * 256);
#pragma unroll 4
    for (int k4 = 0; k4 < 64; ++k4) {
        float4 w = wr[k4];
#pragma unroll
        for (int r = 0; r < 8; ++r) {
            const float* gg = s_G + r * 256 + k4 * 4;
            acc[r] += w.x * gg[0] + w.y * gg[1] + w.z * gg[2] + w.w * gg[3];
        }
    }
    const float cb = cb2[d];
#pragma unroll
    for (int r = 0; r < 8; ++r)
        out[(i0 + r) * 256 + d] = acc[r] + cb * g_ssum[i0 + r];
}

// ---------------------------------------------------------------------------
extern "C" void kernel_launch(void* const* d_in, const int* in_sizes, int n_in,
                              void* d_out, int out_size) {
    (void)in_sizes; (void)n_in; (void)out_size;
    const float* obj   = (const float*)d_in[0];
    const float* bbox  = (const float*)d_in[1];
    const float* mask  = (const float*)d_in[2];
    const float* w1    = (const float*)d_in[3];
    const float* b1    = (const float*)d_in[4];
    const float* gamma = (const float*)d_in[5];
    const float* beta  = (const float*)d_in[6];
    const float* mean  = (const float*)d_in[7];
    const float* var   = (const float*)d_in[8];
    const float* w2    = (const float*)d_in[9];
    const float* b2    = (const float*)d_in[10];
    const float* cw1   = (const float*)d_in[11];
    const float* cb1   = (const float*)d_in[12];
    const float* cw2   = (const float*)d_in[13];
    const float* cb2   = (const float*)d_in[14];
    float* out = (float*)d_out;

    k_rowmlp<<<128, 256>>>(obj, w1, b1, cw1, cb1);
    k_bfrag<<<dim3(8, 4, 2), 128>>>(w1, cw1);
    k_uc0<<<1, 256>>>(gamma, beta, mean, var, w2, b2);
    k_afrag<<<dim3(32, 512), 256>>>(bbox);
    k_pass1_m<<<dim3(8, 512), 256>>>();
    k_conf<<<64, 256>>>(mask);
    k_pass2_m<<<dim3(8, 512), 256>>>();
    k_final<<<64, 256>>>(cw2, cb2, out);
}

// round 16
// speedup vs baseline: 4.4900x; 1.1820x over previous
#include <cuda_runtime.h>
#include <cuda_bf16.h>
#include <cstdint>

// ---------------------------------------------------------------------------
// PositionRelationEncodeUnit_GCN — mma.sync (bf16 hi-term) implementation
//
//   h[i,j,:]  = A1[i,:] + B1[j,:] + bbox[i,j,:] @ w1c^T
//   logit[i,j]= c0 + sum_h u[h]*leaky(h[i,j,h])
//   conf      = renorm(mask * softmax_j(logit))
//   g[i,j,:]  = relu(Ac[i,:] + Bc[j,:] + bbox[i,j,:] @ cw1c^T)
//   G[i,:]    = sum_j conf[i,j]*g[i,j,:]
//   out[i,:]  = G[i,:] @ cw2^T + cb2 * sum_j conf[i,j]
//
// Per-pair GEMMs on HMMA (mma.sync.m16n8k16.bf16, fp32 acc), single term:
//   A@B ≈ Ahi@Bhi  (bf16-rounded operands; empirically ~1e-4 rel err after
//   softmax/reduce, well under the 1e-3 gate). The legacy HMMA pipe issues at
//   a fixed rate, so MMA count == runtime; 1 term is the fast point.
// Block = 64 j x 256 h, 8 warps (2 wj x 4 wh), warp tile 32j x 64h.
// ---------------------------------------------------------------------------

#define NN   512
#define HID  256
#define DB   128

// ----- device scratch -----
__device__ __align__(16) float g_A1[NN * HID];
__device__ __align__(16) float g_B1[NN * HID];
__device__ __align__(16) float g_Ac[NN * HID];
__device__ __align__(16) float g_Bc[NN * HID];
__device__ float g_u[HID];
__device__ float g_c0;
__device__ __align__(16) float g_logits[NN * NN];
__device__ __align__(16) float g_conf[NN * NN];
__device__ float g_ssum[NN];
__device__ __align__(16) float g_Gpart[8 * NN * HID];

// A fragments (bf16 hi): [i (512)][jm (32)][kt (8)][lane (32)] x uint4
__device__ uint4 g_Afh[NN * 32 * 8 * 32];
// B fragments (bf16 hi): [mat (2)][ ((kt*4+hw)*4+np)*32 + lane ] x uint4
__device__ uint4 g_Bf[2][8 * 4 * 4 * 32];

// ----- helpers -----
__device__ __forceinline__ uint32_t pk2(__nv_bfloat16 a, __nv_bfloat16 b) {
    return (uint32_t)__bfloat16_as_ushort(a) |
           ((uint32_t)__bfloat16_as_ushort(b) << 16);
}
__device__ __forceinline__ void mma16816(float* c, const uint4& a,
                                         uint32_t b0, uint32_t b1) {
    asm volatile(
        "mma.sync.aligned.m16n8k16.row.col.f32.bf16.bf16.f32 "
        "{%0,%1,%2,%3}, {%4,%5,%6,%7}, {%8,%9}, {%0,%1,%2,%3};"
        : "+f"(c[0]), "+f"(c[1]), "+f"(c[2]), "+f"(c[3])
        : "r"(a.x), "r"(a.y), "r"(a.z), "r"(a.w), "r"(b0), "r"(b1));
}

// ---------------------------------------------------------------------------
// Precompute A1/B1/Ac/Bc (object-feature halves of the first Linears)
// ---------------------------------------------------------------------------
__global__ void __launch_bounds__(256) k_rowmlp(const float* __restrict__ obj,
                                                const float* __restrict__ w1,
                                                const float* __restrict__ b1,
                                                const float* __restrict__ cw1,
                                                const float* __restrict__ cb1) {
    __shared__ float s_obj[4 * 256];
    const int i0 = blockIdx.x * 4;
    const int tid = threadIdx.x;
#pragma unroll
    for (int r = 0; r < 4; ++r) s_obj[r * 256 + tid] = obj[(i0 + r) * 256 + tid];
    __syncthreads();

    const int h = tid;
    float aA[4] = {0.f, 0.f, 0.f, 0.f}, aB[4] = {0.f, 0.f, 0.f, 0.f};
    float aC[4] = {0.f, 0.f, 0.f, 0.f}, aD[4] = {0.f, 0.f, 0.f, 0.f};
    const float4* wr = (const float4*)(w1 + (size_t)h * 640);
    const float4* cr = (const float4*)(cw1 + (size_t)h * 640);
#pragma unroll 4
    for (int k4 = 0; k4 < 64; ++k4) {
        float4 wa = wr[k4], wb = wr[64 + k4];
        float4 ca = cr[k4], cb = cr[64 + k4];
#pragma unroll
        for (int r = 0; r < 4; ++r) {
            const float* o = s_obj + r * 256 + k4 * 4;
            float o0 = o[0], o1 = o[1], o2 = o[2], o3 = o[3];
            aA[r] += wa.x * o0 + wa.y * o1 + wa.z * o2 + wa.w * o3;
            aB[r] += wb.x * o0 + wb.y * o1 + wb.z * o2 + wb.w * o3;
            aC[r] += ca.x * o0 + ca.y * o1 + ca.z * o2 + ca.w * o3;
            aD[r] += cb.x * o0 + cb.y * o1 + cb.z * o2 + cb.w * o3;
        }
    }
    const float bb1 = b1[h], bcb1 = cb1[h];
#pragma unroll
    for (int r = 0; r < 4; ++r) {
        g_A1[(i0 + r) * 256 + h] = aA[r] + bb1;
        g_B1[(i0 + r) * 256 + h] = aB[r];
        g_Ac[(i0 + r) * 256 + h] = aC[r] + bcb1;
        g_Bc[(i0 + r) * 256 + h] = aD[r];
    }
}

// Fold BN+w2 into (u, c0)
__global__ void k_uc0(const float* __restrict__ gamma, const float* __restrict__ beta,
                      const float* __restrict__ mean, const float* __restrict__ var,
                      const float* __restrict__ w2, const float* __restrict__ b2) {
    const int h = threadIdx.x;
    float rs = rsqrtf(var[h] + 1e-5f);
    float sc = gamma[h] * rs;
    g_u[h] = sc * w2[h];
    float t = (beta[h] - mean[h] * sc) * w2[h];
    __shared__ float sr[256];
    sr[h] = t;
    __syncthreads();
    for (int s = 128; s > 0; s >>= 1) {
        if (h < s) sr[h] += sr[h + s];
        __syncthreads();
    }
    if (h == 0) g_c0 = sr[0] + b2[0];
}

// ---------------------------------------------------------------------------
// B fragments (hi only). grid (8 kt, 4 hw, 2 mat), block 128 (4 np x 32 lanes)
// ---------------------------------------------------------------------------
__global__ void k_bfrag(const float* __restrict__ w1, const float* __restrict__ cw1) {
    const int kt = blockIdx.x, hw = blockIdx.y, mat = blockIdx.z;
    const int np = threadIdx.x >> 5, lane = threadIdx.x & 31;
    const int g = lane >> 2, t4 = lane & 3;
    const float* W = mat ? cw1 : w1;
    const int n0 = hw * 64 + np * 16 + g;
    const int n1 = n0 + 8;
    const int k0 = kt * 16 + t4 * 2;
    const float* r0 = W + (size_t)n0 * 640 + 512;
    const float* r1 = W + (size_t)n1 * 640 + 512;
    const int idx = ((kt * 4 + hw) * 4 + np) * 32 + lane;
    g_Bf[mat][idx] = make_uint4(
        pk2(__float2bfloat16(r0[k0]), __float2bfloat16(r0[k0 + 1])),
        pk2(__float2bfloat16(r0[k0 + 8]), __float2bfloat16(r0[k0 + 9])),
        pk2(__float2bfloat16(r1[k0]), __float2bfloat16(r1[k0 + 1])),
        pk2(__float2bfloat16(r1[k0 + 8]), __float2bfloat16(r1[k0 + 9])));
}

// ---------------------------------------------------------------------------
// A fragments (hi only). grid (32 jm, 512 i), block 256 (8 kt x 32 lanes)
// ---------------------------------------------------------------------------
__global__ void __launch_bounds__(256) k_afrag(const float* __restrict__ bbox) {
    const int kt = threadIdx.x >> 5, lane = threadIdx.x & 31;
    const int jm = blockIdx.x, i = blockIdx.y;
    const int g = lane >> 2, t4 = lane & 3;
    const float* base = bbox + ((size_t)i * NN + (size_t)jm * 16) * DB;
    const int c0 = kt * 16 + t4 * 2;
    float2 v00 = *(const float2*)(base + (size_t)g * DB + c0);
    float2 v01 = *(const float2*)(base + (size_t)g * DB + c0 + 8);
    float2 v10 = *(const float2*)(base + (size_t)(g + 8) * DB + c0);
    float2 v11 = *(const float2*)(base + (size_t)(g + 8) * DB + c0 + 8);
    const size_t idx = (((size_t)i * 32 + jm) * 8 + kt) * 32 + lane;
    g_Afh[idx] = make_uint4(
        pk2(__float2bfloat16(v00.x), __float2bfloat16(v00.y)),
        pk2(__float2bfloat16(v10.x), __float2bfloat16(v10.y)),
        pk2(__float2bfloat16(v01.x), __float2bfloat16(v01.y)),
        pk2(__float2bfloat16(v11.x), __float2bfloat16(v11.y)));
}

// ---------------------------------------------------------------------------
// Tensor mainloop (single hi term): acc[2 mm][8 nt][4]
// Warp tile 32j x 64h, K=128. Per kt: prefetch next A+B, then 16 MMAs.
// ---------------------------------------------------------------------------
__device__ __forceinline__ void mma_mainloop(float acc[2][8][4], int i, int jm0,
                                             int wh, int lane, int mat) {
    const uint4* pa0 = g_Afh + (((size_t)i * 32 + jm0) * 8) * 32 + lane;
    const uint4* pa1 = pa0 + 8 * 32;
    const uint4* pb = g_Bf[mat] + wh * 128 + lane;

    uint4 a0 = pa0[0];
    uint4 a1 = pa1[0];
    uint4 b0 = pb[0];
    uint4 b1 = pb[32];
    uint4 b2 = pb[64];
    uint4 b3 = pb[96];

#pragma unroll
    for (int kt = 0; kt < 8; ++kt) {
        // prefetch next kt operands (independent of current MMAs)
        uint4 a0n = a0, a1n = a1, b0n = b0, b1n = b1, b2n = b2, b3n = b3;
        if (kt < 7) {
            a0n = pa0[(kt + 1) * 32];
            a1n = pa1[(kt + 1) * 32];
            b0n = pb[(kt + 1) * 512 + 0];
            b1n = pb[(kt + 1) * 512 + 32];
            b2n = pb[(kt + 1) * 512 + 64];
            b3n = pb[(kt + 1) * 512 + 96];
        }

        mma16816(acc[0][0], a0, b0.x, b0.y);
        mma16816(acc[1][0], a1, b0.x, b0.y);
        mma16816(acc[0][1], a0, b0.z, b0.w);
        mma16816(acc[1][1], a1, b0.z, b0.w);
        mma16816(acc[0][2], a0, b1.x, b1.y);
        mma16816(acc[1][2], a1, b1.x, b1.y);
        mma16816(acc[0][3], a0, b1.z, b1.w);
        mma16816(acc[1][3], a1, b1.z, b1.w);
        mma16816(acc[0][4], a0, b2.x, b2.y);
        mma16816(acc[1][4], a1, b2.x, b2.y);
        mma16816(acc[0][5], a0, b2.z, b2.w);
        mma16816(acc[1][5], a1, b2.z, b2.w);
        mma16816(acc[0][6], a0, b3.x, b3.y);
        mma16816(acc[1][6], a1, b3.x, b3.y);
        mma16816(acc[0][7], a0, b3.z, b3.w);
        mma16816(acc[1][7], a1, b3.z, b3.w);

        a0 = a0n; a1 = a1n;
        b0 = b0n; b1 = b1n; b2 = b2n; b3 = b3n;
    }
}

// ---------------------------------------------------------------------------
// Pass 1: logits. grid (8 jt, 512 i), block 256 (2 wj x 4 wh warps)
// ---------------------------------------------------------------------------
__global__ void __launch_bounds__(256, 2) k_pass1_m() {
    __shared__ float s_u[256], s_a1[256], sp[4][64];
    const int tid = threadIdx.x;
    const int lane = tid & 31, w = tid >> 5, wj = w >> 2, wh = w & 3;
    const int g = lane >> 2, t4 = lane & 3;
    const int jt = blockIdx.x, i = blockIdx.y;
    s_u[tid] = g_u[tid];
    s_a1[tid] = g_A1[i * 256 + tid];
    __syncthreads();

    float acc[2][8][4];
#pragma unroll
    for (int a = 0; a < 2; ++a)
#pragma unroll
        for (int b = 0; b < 8; ++b)
#pragma unroll
            for (int c = 0; c < 4; ++c) acc[a][b][c] = 0.f;

    mma_mainloop(acc, i, jt * 4 + wj * 2, wh, lane, 0);

    const float c0v = g_c0;
#pragma unroll
    for (int mm = 0; mm < 2; ++mm) {
#pragma unroll
        for (int hf = 0; hf < 2; ++hf) {
            const int jl = wj * 32 + mm * 16 + g + hf * 8;     // 0..63
            const int jgl = jt * 64 + jl;
            const float* b1row = g_B1 + (size_t)jgl * 256;
            float s = 0.f;
#pragma unroll
            for (int nt = 0; nt < 8; ++nt) {
                const int h0 = wh * 64 + nt * 8 + t4 * 2;
                float2 bv = *(const float2*)(b1row + h0);
                float x = acc[mm][nt][hf * 2 + 0] + s_a1[h0] + bv.x;
                x = x > 0.f ? x : 0.01f * x;
                float y = acc[mm][nt][hf * 2 + 1] + s_a1[h0 + 1] + bv.y;
                y = y > 0.f ? y : 0.01f * y;
                s += s_u[h0] * x + s_u[h0 + 1] * y;
            }
            s += __shfl_xor_sync(0xffffffffu, s, 1);
            s += __shfl_xor_sync(0xffffffffu, s, 2);
            if (t4 == 0) sp[wh][jl] = s;
        }
    }
    __syncthreads();
    if (tid < 64) {
        float l = sp[0][tid] + sp[1][tid] + sp[2][tid] + sp[3][tid] + c0v;
        g_logits[(size_t)i * NN + jt * 64 + tid] = l;
    }
}

// ---------------------------------------------------------------------------
// Softmax + mask renorm: one warp per row, shfl-only. grid 64, block 256.
// ---------------------------------------------------------------------------
__global__ void __launch_bounds__(256) k_conf(const float* __restrict__ mask) {
    const int w = threadIdx.x >> 5, lane = threadIdx.x & 31;
    const int i = blockIdx.x * 8 + w;

    const float4* Lr = (const float4*)(g_logits + (size_t)i * NN) + lane * 4;
    float4 v0 = Lr[0], v1 = Lr[1], v2 = Lr[2], v3 = Lr[3];

    float m = fmaxf(fmaxf(fmaxf(v0.x, v0.y), fmaxf(v0.z, v0.w)),
                    fmaxf(fmaxf(v1.x, v1.y), fmaxf(v1.z, v1.w)));
    m = fmaxf(m, fmaxf(fmaxf(fmaxf(v2.x, v2.y), fmaxf(v2.z, v2.w)),
                       fmaxf(fmaxf(v3.x, v3.y), fmaxf(v3.z, v3.w))));
#pragma unroll
    for (int off = 16; off > 0; off >>= 1)
        m = fmaxf(m, __shfl_xor_sync(0xffffffffu, m, off));

    float e[16];
    e[0] = __expf(v0.x - m);  e[1] = __expf(v0.y - m);
    e[2] = __expf(v0.z - m);  e[3] = __expf(v0.w - m);
    e[4] = __expf(v1.x - m);  e[5] = __expf(v1.y - m);
    e[6] = __expf(v1.z - m);  e[7] = __expf(v1.w - m);
    e[8] = __expf(v2.x - m);  e[9] = __expf(v2.y - m);
    e[10] = __expf(v2.z - m); e[11] = __expf(v2.w - m);
    e[12] = __expf(v3.x - m); e[13] = __expf(v3.y - m);
    e[14] = __expf(v3.z - m); e[15] = __expf(v3.w - m);

    float E = 0.f;
#pragma unroll
    for (int q = 0; q < 16; ++q) E += e[q];
#pragma unroll
    for (int off = 16; off > 0; off >>= 1)
        E += __shfl_xor_sync(0xffffffffu, E, off);

    const float4* Mr = (const float4*)(mask + (size_t)i * NN) + lane * 4;
    float em[16];
    float EM = 0.f;
#pragma unroll
    for (int q4 = 0; q4 < 4; ++q4) {
        float4 mv = Mr[q4];
        em[q4 * 4 + 0] = e[q4 * 4 + 0] * mv.x;
        em[q4 * 4 + 1] = e[q4 * 4 + 1] * mv.y;
        em[q4 * 4 + 2] = e[q4 * 4 + 2] * mv.z;
        em[q4 * 4 + 3] = e[q4 * 4 + 3] * mv.w;
        EM += em[q4 * 4 + 0] + em[q4 * 4 + 1] + em[q4 * 4 + 2] + em[q4 * 4 + 3];
    }
#pragma unroll
    for (int off = 16; off > 0; off >>= 1)
        EM += __shfl_xor_sync(0xffffffffu, EM, off);

    const float inv = 1.f / (EM + 1e-8f * E);
    float4* Cw = (float4*)(g_conf + (size_t)i * NN) + lane * 4;
#pragma unroll
    for (int q4 = 0; q4 < 4; ++q4)
        Cw[q4] = make_float4(em[q4 * 4 + 0] * inv, em[q4 * 4 + 1] * inv,
                             em[q4 * 4 + 2] * inv, em[q4 * 4 + 3] * inv);
    if (lane == 0) g_ssum[i] = EM * inv;
}

// ---------------------------------------------------------------------------
// Pass 2: conv + conf-weighted j-reduce. grid (8 jt, 512 i), block 256
// ---------------------------------------------------------------------------
__global__ void __launch_bounds__(256, 2) k_pass2_m() {
    __shared__ float s_ac[256], gp[2][256];
    const int tid = threadIdx.x;
    const int lane = tid & 31, w = tid >> 5, wj = w >> 2, wh = w & 3;
    const int g = lane >> 2, t4 = lane & 3;
    const int jt = blockIdx.x, i = blockIdx.y;
    s_ac[tid] = g_Ac[i * 256 + tid];
    __syncthreads();

    float acc[2][8][4];
#pragma unroll
    for (int a = 0; a < 2; ++a)
#pragma unroll
        for (int b = 0; b < 8; ++b)
#pragma unroll
            for (int c = 0; c < 4; ++c) acc[a][b][c] = 0.f;

    mma_mainloop(acc, i, jt * 4 + wj * 2, wh, lane, 1);

    float hs[8][2];
#pragma unroll
    for (int nt = 0; nt < 8; ++nt) { hs[nt][0] = 0.f; hs[nt][1] = 0.f; }

#pragma unroll
    for (int mm = 0; mm < 2; ++mm) {
#pragma unroll
        for (int hf = 0; hf < 2; ++hf) {
            const int jl = wj * 32 + mm * 16 + g + hf * 8;
            const int jgl = jt * 64 + jl;
            const float c = g_conf[(size_t)i * NN + jgl];
            const float* bcrow = g_Bc + (size_t)jgl * 256;
#pragma unroll
            for (int nt = 0; nt < 8; ++nt) {
                const int h0 = wh * 64 + nt * 8 + t4 * 2;
                float2 bv = *(const float2*)(bcrow + h0);
                float x = fmaxf(acc[mm][nt][hf * 2 + 0] + s_ac[h0] + bv.x, 0.f);
                float y = fmaxf(acc[mm][nt][hf * 2 + 1] + s_ac[h0 + 1] + bv.y, 0.f);
                hs[nt][0] += c * x;
                hs[nt][1] += c * y;
            }
        }
    }
#pragma unroll
    for (int nt = 0; nt < 8; ++nt) {
#pragma unroll
        for (int r = 0; r < 2; ++r) {
            float v = hs[nt][r];
            v += __shfl_xor_sync(0xffffffffu, v, 4);
            v += __shfl_xor_sync(0xffffffffu, v, 8);
            v += __shfl_xor_sync(0xffffffffu, v, 16);
            if (g == 0) gp[wj][wh * 64 + nt * 8 + t4 * 2 + r] = v;
        }
    }
    __syncthreads();
    g_Gpart[((size_t)jt * NN + i) * 256 + tid] = gp[0][tid] + gp[1][tid];
}

// ---------------------------------------------------------------------------
// Final: reduce 8 j-tile partials + tiny GEMM.
// out[i,d] = (sum_c Gpart[c,i,:])·cw2[d,:] + cb2[d]*ssum[i]. grid 64 (8 i each)
// ---------------------------------------------------------------------------
__global__ void __launch_bounds__(256) k_final(const float* __restrict__ cw2,
                                               const float* __restrict__ cb2,
                                               float* __restrict__ out) {
    __shared__ float s_G[8 * 256];
    const int i0 = blockIdx.x * 8;
    const int tid = threadIdx.x;
#pragma unroll
    for (int r = 0; r < 8; ++r) {
        float s = 0.f;
#pragma unroll
        for (int c = 0; c < 8; ++c)
            s += g_Gpart[((size_t)c * NN + (i0 + r)) * 256 + tid];
        s_G[r * 256 + tid] = s;
    }
    __syncthreads();

    const int d = tid;
    float acc[8];
#pragma unroll
    for (int r = 0; r < 8; ++r) acc[r] = 0.f;
    const float4* wr = (const float4*)(cw2 + (size_t)d * 256);
#pragma unroll 4
    for (int k4 = 0; k4 < 64; ++k4) {
        float4 w = wr[k4];
#pragma unroll
        for (int r = 0; r < 8; ++r) {
            const float* gg = s_G + r * 256 + k4 * 4;
            acc[r] += w.x * gg[0] + w.y * gg[1] + w.z * gg[2] + w.w * gg[3];
        }
    }
    const float cb = cb2[d];
#pragma unroll
    for (int r = 0; r < 8; ++r)
        out[(i0 + r) * 256 + d] = acc[r] + cb * g_ssum[i0 + r];
}

// ---------------------------------------------------------------------------
extern "C" void kernel_launch(void* const* d_in, const int* in_sizes, int n_in,
                              void* d_out, int out_size) {
    (void)in_sizes; (void)n_in; (void)out_size;
    const float* obj   = (const float*)d_in[0];
    const float* bbox  = (const float*)d_in[1];
    const float* mask  = (const float*)d_in[2];
    const float* w1    = (const float*)d_in[3];
    const float* b1    = (const float*)d_in[4];
    const float* gamma = (const float*)d_in[5];
    const float* beta  = (const float*)d_in[6];
    const float* mean  = (const float*)d_in[7];
    const float* var   = (const float*)d_in[8];
    const float* w2    = (const float*)d_in[9];
    const float* b2    = (const float*)d_in[10];
    const float* cw1   = (const float*)d_in[11];
    const float* cb1   = (const float*)d_in[12];
    const float* cw2   = (const float*)d_in[13];
    const float* cb2   = (const float*)d_in[14];
    float* out = (float*)d_out;

    k_rowmlp<<<128, 256>>>(obj, w1, b1, cw1, cb1);
    k_bfrag<<<dim3(8, 4, 2), 128>>>(w1, cw1);
    k_uc0<<<1, 256>>>(gamma, beta, mean, var, w2, b2);
    k_afrag<<<dim3(32, 512), 256>>>(bbox);
    k_pass1_m<<<dim3(8, 512), 256>>>();
    k_conf<<<64, 256>>>(mask);
    k_pass2_m<<<dim3(8, 512), 256>>>();
    k_final<<<64, 256>>>(cw2, cb2, out);
}

// round 17
// speedup vs baseline: 4.5417x; 1.0115x over previous
#include <cuda_runtime.h>
#include <cuda_bf16.h>
#include <cstdint>

// ---------------------------------------------------------------------------
// PositionRelationEncodeUnit_GCN — mma.sync (bf16 hi-term) implementation
//
//   h[i,j,:]  = A1[i,:] + B1[j,:] + bbox[i,j,:] @ w1c^T
//   logit[i,j]= c0 + sum_h u[h]*leaky(h[i,j,h])
//   conf      = renorm(mask * softmax_j(logit))
//   g[i,j,:]  = relu(Ac[i,:] + Bc[j,:] + bbox[i,j,:] @ cw1c^T)
//   G[i,:]    = sum_j conf[i,j]*g[i,j,:]
//   out[i,:]  = G[i,:] @ cw2^T + cb2 * sum_j conf[i,j]
//
// Per-pair GEMMs on HMMA (mma.sync.m16n8k16.bf16, fp32 acc), bf16 operands
// (rel_err ~1e-4 after softmax/reduce, under the 1e-3 gate).
// A fragments are staged block-wide in SMEM (16 KB, loaded once, coalesced),
// killing the 4x wh-redundant A LDG traffic; B streams through L1 with a
// register prefetch pipeline.
// Block = 64 j x 256 h, 8 warps (2 wj x 4 wh), warp tile 32j x 64h.
// ---------------------------------------------------------------------------

#define NN   512
#define HID  256
#define DB   128

// ----- device scratch -----
__device__ __align__(16) float g_A1[NN * HID];
__device__ __align__(16) float g_B1[NN * HID];
__device__ __align__(16) float g_Ac[NN * HID];
__device__ __align__(16) float g_Bc[NN * HID];
__device__ float g_u[HID];
__device__ float g_c0;
__device__ __align__(16) float g_logits[NN * NN];
__device__ __align__(16) float g_conf[NN * NN];
__device__ float g_ssum[NN];
__device__ __align__(16) float g_Gpart[8 * NN * HID];

// A fragments (bf16 hi): [i (512)][jm (32)][kt (8)][lane (32)] x uint4
__device__ uint4 g_Afh[NN * 32 * 8 * 32];
// B fragments (bf16 hi): [mat (2)][ ((kt*4+hw)*4+np)*32 + lane ] x uint4
__device__ uint4 g_Bf[2][8 * 4 * 4 * 32];

// ----- helpers -----
__device__ __forceinline__ uint32_t pk2(__nv_bfloat16 a, __nv_bfloat16 b) {
    return (uint32_t)__bfloat16_as_ushort(a) |
           ((uint32_t)__bfloat16_as_ushort(b) << 16);
}
__device__ __forceinline__ void mma16816(float* c, const uint4& a,
                                         uint32_t b0, uint32_t b1) {
    asm volatile(
        "mma.sync.aligned.m16n8k16.row.col.f32.bf16.bf16.f32 "
        "{%0,%1,%2,%3}, {%4,%5,%6,%7}, {%8,%9}, {%0,%1,%2,%3};"
        : "+f"(c[0]), "+f"(c[1]), "+f"(c[2]), "+f"(c[3])
        : "r"(a.x), "r"(a.y), "r"(a.z), "r"(a.w), "r"(b0), "r"(b1));
}

// ---------------------------------------------------------------------------
// Precompute A1/B1/Ac/Bc (object-feature halves of the first Linears)
// ---------------------------------------------------------------------------
__global__ void __launch_bounds__(256) k_rowmlp(const float* __restrict__ obj,
                                                const float* __restrict__ w1,
                                                const float* __restrict__ b1,
                                                const float* __restrict__ cw1,
                                                const float* __restrict__ cb1) {
    __shared__ float s_obj[4 * 256];
    const int i0 = blockIdx.x * 4;
    const int tid = threadIdx.x;
#pragma unroll
    for (int r = 0; r < 4; ++r) s_obj[r * 256 + tid] = obj[(i0 + r) * 256 + tid];
    __syncthreads();

    const int h = tid;
    float aA[4] = {0.f, 0.f, 0.f, 0.f}, aB[4] = {0.f, 0.f, 0.f, 0.f};
    float aC[4] = {0.f, 0.f, 0.f, 0.f}, aD[4] = {0.f, 0.f, 0.f, 0.f};
    const float4* wr = (const float4*)(w1 + (size_t)h * 640);
    const float4* cr = (const float4*)(cw1 + (size_t)h * 640);
#pragma unroll 4
    for (int k4 = 0; k4 < 64; ++k4) {
        float4 wa = wr[k4], wb = wr[64 + k4];
        float4 ca = cr[k4], cb = cr[64 + k4];
#pragma unroll
        for (int r = 0; r < 4; ++r) {
            const float* o = s_obj + r * 256 + k4 * 4;
            float o0 = o[0], o1 = o[1], o2 = o[2], o3 = o[3];
            aA[r] += wa.x * o0 + wa.y * o1 + wa.z * o2 + wa.w * o3;
            aB[r] += wb.x * o0 + wb.y * o1 + wb.z * o2 + wb.w * o3;
            aC[r] += ca.x * o0 + ca.y * o1 + ca.z * o2 + ca.w * o3;
            aD[r] += cb.x * o0 + cb.y * o1 + cb.z * o2 + cb.w * o3;
        }
    }
    const float bb1 = b1[h], bcb1 = cb1[h];
#pragma unroll
    for (int r = 0; r < 4; ++r) {
        g_A1[(i0 + r) * 256 + h] = aA[r] + bb1;
        g_B1[(i0 + r) * 256 + h] = aB[r];
        g_Ac[(i0 + r) * 256 + h] = aC[r] + bcb1;
        g_Bc[(i0 + r) * 256 + h] = aD[r];
    }
}

// Fold BN+w2 into (u, c0)
__global__ void k_uc0(const float* __restrict__ gamma, const float* __restrict__ beta,
                      const float* __restrict__ mean, const float* __restrict__ var,
                      const float* __restrict__ w2, const float* __restrict__ b2) {
    const int h = threadIdx.x;
    float rs = rsqrtf(var[h] + 1e-5f);
    float sc = gamma[h] * rs;
    g_u[h] = sc * w2[h];
    float t = (beta[h] - mean[h] * sc) * w2[h];
    __shared__ float sr[256];
    sr[h] = t;
    __syncthreads();
    for (int s = 128; s > 0; s >>= 1) {
        if (h < s) sr[h] += sr[h + s];
        __syncthreads();
    }
    if (h == 0) g_c0 = sr[0] + b2[0];
}

// ---------------------------------------------------------------------------
// B fragments (hi only). grid (8 kt, 4 hw, 2 mat), block 128 (4 np x 32 lanes)
// ---------------------------------------------------------------------------
__global__ void k_bfrag(const float* __restrict__ w1, const float* __restrict__ cw1) {
    const int kt = blockIdx.x, hw = blockIdx.y, mat = blockIdx.z;
    const int np = threadIdx.x >> 5, lane = threadIdx.x & 31;
    const int g = lane >> 2, t4 = lane & 3;
    const float* W = mat ? cw1 : w1;
    const int n0 = hw * 64 + np * 16 + g;
    const int n1 = n0 + 8;
    const int k0 = kt * 16 + t4 * 2;
    const float* r0 = W + (size_t)n0 * 640 + 512;
    const float* r1 = W + (size_t)n1 * 640 + 512;
    const int idx = ((kt * 4 + hw) * 4 + np) * 32 + lane;
    g_Bf[mat][idx] = make_uint4(
        pk2(__float2bfloat16(r0[k0]), __float2bfloat16(r0[k0 + 1])),
        pk2(__float2bfloat16(r0[k0 + 8]), __float2bfloat16(r0[k0 + 9])),
        pk2(__float2bfloat16(r1[k0]), __float2bfloat16(r1[k0 + 1])),
        pk2(__float2bfloat16(r1[k0 + 8]), __float2bfloat16(r1[k0 + 9])));
}

// ---------------------------------------------------------------------------
// A fragments (hi only). grid (32 jm, 512 i), block 256 (8 kt x 32 lanes)
// ---------------------------------------------------------------------------
__global__ void __launch_bounds__(256) k_afrag(const float* __restrict__ bbox) {
    const int kt = threadIdx.x >> 5, lane = threadIdx.x & 31;
    const int jm = blockIdx.x, i = blockIdx.y;
    const int g = lane >> 2, t4 = lane & 3;
    const float* base = bbox + ((size_t)i * NN + (size_t)jm * 16) * DB;
    const int c0 = kt * 16 + t4 * 2;
    float2 v00 = *(const float2*)(base + (size_t)g * DB + c0);
    float2 v01 = *(const float2*)(base + (size_t)g * DB + c0 + 8);
    float2 v10 = *(const float2*)(base + (size_t)(g + 8) * DB + c0);
    float2 v11 = *(const float2*)(base + (size_t)(g + 8) * DB + c0 + 8);
    const size_t idx = (((size_t)i * 32 + jm) * 8 + kt) * 32 + lane;
    g_Afh[idx] = make_uint4(
        pk2(__float2bfloat16(v00.x), __float2bfloat16(v00.y)),
        pk2(__float2bfloat16(v10.x), __float2bfloat16(v10.y)),
        pk2(__float2bfloat16(v01.x), __float2bfloat16(v01.y)),
        pk2(__float2bfloat16(v11.x), __float2bfloat16(v11.y)));
}

// ---------------------------------------------------------------------------
// Cooperative A-stage: the block's whole A working set (4 jm x 8 kt x 32
// lanes x uint4 = 16 KB) is contiguous in g_Afh. Coalesced uint4 copy.
// ---------------------------------------------------------------------------
__device__ __forceinline__ void stage_A(uint4* s_A, int i, int jt, int tid) {
    const uint4* src = g_Afh + ((size_t)i * 32 + jt * 4) * 256;
#pragma unroll
    for (int it = 0; it < 4; ++it) s_A[it * 256 + tid] = src[it * 256 + tid];
}

// ---------------------------------------------------------------------------
// Tensor mainloop: acc[2 mm][8 nt][4]; warp tile 32j x 64h, K=128.
// A from SMEM (conflict-free LDS.128), B from gmem (L1-resident) with a
// one-step register prefetch pipeline.
// ---------------------------------------------------------------------------
__device__ __forceinline__ void mma_mainloop(float acc[2][8][4],
                                             const uint4* __restrict__ s_A,
                                             int wj, int wh, int lane, int mat) {
    const uint4* sa0 = s_A + (wj * 2 + 0) * 256 + lane;
    const uint4* sa1 = s_A + (wj * 2 + 1) * 256 + lane;
    const uint4* pb = g_Bf[mat] + wh * 128 + lane;

    uint4 a0 = sa0[0];
    uint4 a1 = sa1[0];
    uint4 b0 = pb[0];
    uint4 b1 = pb[32];
    uint4 b2 = pb[64];
    uint4 b3 = pb[96];

#pragma unroll
    for (int kt = 0; kt < 8; ++kt) {
        // prefetch next kt operands (independent of current MMAs)
        uint4 a0n = a0, a1n = a1, b0n = b0, b1n = b1, b2n = b2, b3n = b3;
        if (kt < 7) {
            a0n = sa0[(kt + 1) * 32];
            a1n = sa1[(kt + 1) * 32];
            b0n = pb[(kt + 1) * 512 + 0];
            b1n = pb[(kt + 1) * 512 + 32];
            b2n = pb[(kt + 1) * 512 + 64];
            b3n = pb[(kt + 1) * 512 + 96];
        }

        mma16816(acc[0][0], a0, b0.x, b0.y);
        mma16816(acc[1][0], a1, b0.x, b0.y);
        mma16816(acc[0][1], a0, b0.z, b0.w);
        mma16816(acc[1][1], a1, b0.z, b0.w);
        mma16816(acc[0][2], a0, b1.x, b1.y);
        mma16816(acc[1][2], a1, b1.x, b1.y);
        mma16816(acc[0][3], a0, b1.z, b1.w);
        mma16816(acc[1][3], a1, b1.z, b1.w);
        mma16816(acc[0][4], a0, b2.x, b2.y);
        mma16816(acc[1][4], a1, b2.x, b2.y);
        mma16816(acc[0][5], a0, b2.z, b2.w);
        mma16816(acc[1][5], a1, b2.z, b2.w);
        mma16816(acc[0][6], a0, b3.x, b3.y);
        mma16816(acc[1][6], a1, b3.x, b3.y);
        mma16816(acc[0][7], a0, b3.z, b3.w);
        mma16816(acc[1][7], a1, b3.z, b3.w);

        a0 = a0n; a1 = a1n;
        b0 = b0n; b1 = b1n; b2 = b2n; b3 = b3n;
    }
}

// ---------------------------------------------------------------------------
// Pass 1: logits. grid (8 jt, 512 i), block 256 (2 wj x 4 wh warps)
// ---------------------------------------------------------------------------
__global__ void __launch_bounds__(256, 2) k_pass1_m() {
    __shared__ __align__(16) uint4 s_A[1024];   // 16 KB
    __shared__ float s_u[256], s_a1[256], sp[4][64];
    const int tid = threadIdx.x;
    const int lane = tid & 31, w = tid >> 5, wj = w >> 2, wh = w & 3;
    const int g = lane >> 2, t4 = lane & 3;
    const int jt = blockIdx.x, i = blockIdx.y;
    s_u[tid] = g_u[tid];
    s_a1[tid] = g_A1[i * 256 + tid];
    stage_A(s_A, i, jt, tid);
    __syncthreads();

    float acc[2][8][4];
#pragma unroll
    for (int a = 0; a < 2; ++a)
#pragma unroll
        for (int b = 0; b < 8; ++b)
#pragma unroll
            for (int c = 0; c < 4; ++c) acc[a][b][c] = 0.f;

    mma_mainloop(acc, s_A, wj, wh, lane, 0);

    const float c0v = g_c0;
#pragma unroll
    for (int mm = 0; mm < 2; ++mm) {
#pragma unroll
        for (int hf = 0; hf < 2; ++hf) {
            const int jl = wj * 32 + mm * 16 + g + hf * 8;     // 0..63
            const int jgl = jt * 64 + jl;
            const float* b1row = g_B1 + (size_t)jgl * 256;
            float s = 0.f;
#pragma unroll
            for (int nt = 0; nt < 8; ++nt) {
                const int h0 = wh * 64 + nt * 8 + t4 * 2;
                float2 bv = *(const float2*)(b1row + h0);
                float x = acc[mm][nt][hf * 2 + 0] + s_a1[h0] + bv.x;
                x = x > 0.f ? x : 0.01f * x;
                float y = acc[mm][nt][hf * 2 + 1] + s_a1[h0 + 1] + bv.y;
                y = y > 0.f ? y : 0.01f * y;
                s += s_u[h0] * x + s_u[h0 + 1] * y;
            }
            s += __shfl_xor_sync(0xffffffffu, s, 1);
            s += __shfl_xor_sync(0xffffffffu, s, 2);
            if (t4 == 0) sp[wh][jl] = s;
        }
    }
    __syncthreads();
    if (tid < 64) {
        float l = sp[0][tid] + sp[1][tid] + sp[2][tid] + sp[3][tid] + c0v;
        g_logits[(size_t)i * NN + jt * 64 + tid] = l;
    }
}

// ---------------------------------------------------------------------------
// Softmax + mask renorm: one warp per row, shfl-only. grid 64, block 256.
// ---------------------------------------------------------------------------
__global__ void __launch_bounds__(256) k_conf(const float* __restrict__ mask) {
    const int w = threadIdx.x >> 5, lane = threadIdx.x & 31;
    const int i = blockIdx.x * 8 + w;

    const float4* Lr = (const float4*)(g_logits + (size_t)i * NN) + lane * 4;
    float4 v0 = Lr[0], v1 = Lr[1], v2 = Lr[2], v3 = Lr[3];

    float m = fmaxf(fmaxf(fmaxf(v0.x, v0.y), fmaxf(v0.z, v0.w)),
                    fmaxf(fmaxf(v1.x, v1.y), fmaxf(v1.z, v1.w)));
    m = fmaxf(m, fmaxf(fmaxf(fmaxf(v2.x, v2.y), fmaxf(v2.z, v2.w)),
                       fmaxf(fmaxf(v3.x, v3.y), fmaxf(v3.z, v3.w))));
#pragma unroll
    for (int off = 16; off > 0; off >>= 1)
        m = fmaxf(m, __shfl_xor_sync(0xffffffffu, m, off));

    float e[16];
    e[0] = __expf(v0.x - m);  e[1] = __expf(v0.y - m);
    e[2] = __expf(v0.z - m);  e[3] = __expf(v0.w - m);
    e[4] = __expf(v1.x - m);  e[5] = __expf(v1.y - m);
    e[6] = __expf(v1.z - m);  e[7] = __expf(v1.w - m);
    e[8] = __expf(v2.x - m);  e[9] = __expf(v2.y - m);
    e[10] = __expf(v2.z - m); e[11] = __expf(v2.w - m);
    e[12] = __expf(v3.x - m); e[13] = __expf(v3.y - m);
    e[14] = __expf(v3.z - m); e[15] = __expf(v3.w - m);

    float E = 0.f;
#pragma unroll
    for (int q = 0; q < 16; ++q) E += e[q];
#pragma unroll
    for (int off = 16; off > 0; off >>= 1)
        E += __shfl_xor_sync(0xffffffffu, E, off);

    const float4* Mr = (const float4*)(mask + (size_t)i * NN) + lane * 4;
    float em[16];
    float EM = 0.f;
#pragma unroll
    for (int q4 = 0; q4 < 4; ++q4) {
        float4 mv = Mr[q4];
        em[q4 * 4 + 0] = e[q4 * 4 + 0] * mv.x;
        em[q4 * 4 + 1] = e[q4 * 4 + 1] * mv.y;
        em[q4 * 4 + 2] = e[q4 * 4 + 2] * mv.z;
        em[q4 * 4 + 3] = e[q4 * 4 + 3] * mv.w;
        EM += em[q4 * 4 + 0] + em[q4 * 4 + 1] + em[q4 * 4 + 2] + em[q4 * 4 + 3];
    }
#pragma unroll
    for (int off = 16; off > 0; off >>= 1)
        EM += __shfl_xor_sync(0xffffffffu, EM, off);

    const float inv = 1.f / (EM + 1e-8f * E);
    float4* Cw = (float4*)(g_conf + (size_t)i * NN) + lane * 4;
#pragma unroll
    for (int q4 = 0; q4 < 4; ++q4)
        Cw[q4] = make_float4(em[q4 * 4 + 0] * inv, em[q4 * 4 + 1] * inv,
                             em[q4 * 4 + 2] * inv, em[q4 * 4 + 3] * inv);
    if (lane == 0) g_ssum[i] = EM * inv;
}

// ---------------------------------------------------------------------------
// Pass 2: conv + conf-weighted j-reduce. grid (8 jt, 512 i), block 256
// ---------------------------------------------------------------------------
__global__ void __launch_bounds__(256, 2) k_pass2_m() {
    __shared__ __align__(16) uint4 s_A[1024];   // 16 KB
    __shared__ float s_ac[256], gp[2][256];
    const int tid = threadIdx.x;
    const int lane = tid & 31, w = tid >> 5, wj = w >> 2, wh = w & 3;
    const int g = lane >> 2, t4 = lane & 3;
    const int jt = blockIdx.x, i = blockIdx.y;
    s_ac[tid] = g_Ac[i * 256 + tid];
    stage_A(s_A, i, jt, tid);
    __syncthreads();

    float acc[2][8][4];
#pragma unroll
    for (int a = 0; a < 2; ++a)
#pragma unroll
        for (int b = 0; b < 8; ++b)
#pragma unroll
            for (int c = 0; c < 4; ++c) acc[a][b][c] = 0.f;

    mma_mainloop(acc, s_A, wj, wh, lane, 1);

    float hs[8][2];
#pragma unroll
    for (int nt = 0; nt < 8; ++nt) { hs[nt][0] = 0.f; hs[nt][1] = 0.f; }

#pragma unroll
    for (int mm = 0; mm < 2; ++mm) {
#pragma unroll
        for (int hf = 0; hf < 2; ++hf) {
            const int jl = wj * 32 + mm * 16 + g + hf * 8;
            const int jgl = jt * 64 + jl;
            const float c = g_conf[(size_t)i * NN + jgl];
            const float* bcrow = g_Bc + (size_t)jgl * 256;
#pragma unroll
            for (int nt = 0; nt < 8; ++nt) {
                const int h0 = wh * 64 + nt * 8 + t4 * 2;
                float2 bv = *(const float2*)(bcrow + h0);
                float x = fmaxf(acc[mm][nt][hf * 2 + 0] + s_ac[h0] + bv.x, 0.f);
                float y = fmaxf(acc[mm][nt][hf * 2 + 1] + s_ac[h0 + 1] + bv.y, 0.f);
                hs[nt][0] += c * x;
                hs[nt][1] += c * y;
            }
        }
    }
#pragma unroll
    for (int nt = 0; nt < 8; ++nt) {
#pragma unroll
        for (int r = 0; r < 2; ++r) {
            float v = hs[nt][r];
            v += __shfl_xor_sync(0xffffffffu, v, 4);
            v += __shfl_xor_sync(0xffffffffu, v, 8);
            v += __shfl_xor_sync(0xffffffffu, v, 16);
            if (g == 0) gp[wj][wh * 64 + nt * 8 + t4 * 2 + r] = v;
        }
    }
    __syncthreads();
    g_Gpart[((size_t)jt * NN + i) * 256 + tid] = gp[0][tid] + gp[1][tid];
}

// ---------------------------------------------------------------------------
// Final: reduce 8 j-tile partials + tiny GEMM.
// out[i,d] = (sum_c Gpart[c,i,:])·cw2[d,:] + cb2[d]*ssum[i]. grid 64 (8 i each)
// ---------------------------------------------------------------------------
__global__ void __launch_bounds__(256) k_final(const float* __restrict__ cw2,
                                               const float* __restrict__ cb2,
                                               float* __restrict__ out) {
    __shared__ float s_G[8 * 256];
    const int i0 = blockIdx.x * 8;
    const int tid = threadIdx.x;
#pragma unroll
    for (int r = 0; r < 8; ++r) {
        float s = 0.f;
#pragma unroll
        for (int c = 0; c < 8; ++c)
            s += g_Gpart[((size_t)c * NN + (i0 + r)) * 256 + tid];
        s_G[r * 256 + tid] = s;
    }
    __syncthreads();

    const int d = tid;
    float acc[8];
#pragma unroll
    for (int r = 0; r < 8; ++r) acc[r] = 0.f;
    const float4* wr = (const float4*)(cw2 + (size_t)d * 256);
#pragma unroll 4
    for (int k4 = 0; k4 < 64; ++k4) {
        float4 w = wr[k4];
#pragma unroll
        for (int r = 0; r < 8; ++r) {
            const float* gg = s_G + r * 256 + k4 * 4;
            acc[r] += w.x * gg[0] + w.y * gg[1] + w.z * gg[2] + w.w * gg[3];
        }
    }
    const float cb = cb2[d];
#pragma unroll
    for (int r = 0; r < 8; ++r)
        out[(i0 + r) * 256 + d] = acc[r] + cb * g_ssum[i0 + r];
}

// ---------------------------------------------------------------------------
extern "C" void kernel_launch(void* const* d_in, const int* in_sizes, int n_in,
                              void* d_out, int out_size) {
    (void)in_sizes; (void)n_in; (void)out_size;
    const float* obj   = (const float*)d_in[0];
    const float* bbox  = (const float*)d_in[1];
    const float* mask  = (const float*)d_in[2];
    const float* w1    = (const float*)d_in[3];
    const float* b1    = (const float*)d_in[4];
    const float* gamma = (const float*)d_in[5];
    const float* beta  = (const float*)d_in[6];
    const float* mean  = (const float*)d_in[7];
    const float* var   = (const float*)d_in[8];
    const float* w2    = (const float*)d_in[9];
    const float* b2    = (const float*)d_in[10];
    const float* cw1   = (const float*)d_in[11];
    const float* cb1   = (const float*)d_in[12];
    const float* cw2   = (const float*)d_in[13];
    const float* cb2   = (const float*)d_in[14];
    float* out = (float*)d_out;

    k_rowmlp<<<128, 256>>>(obj, w1, b1, cw1, cb1);
    k_bfrag<<<dim3(8, 4, 2), 128>>>(w1, cw1);
    k_uc0<<<1, 256>>>(gamma, beta, mean, var, w2, b2);
    k_afrag<<<dim3(32, 512), 256>>>(bbox);
    k_pass1_m<<<dim3(8, 512), 256>>>();
    k_conf<<<64, 256>>>(mask);
    k_pass2_m<<<dim3(8, 512), 256>>>();
    k_final<<<64, 256>>>(cw2, cb2, out);
}